// round 13
// baseline (speedup 1.0000x reference)
#include <cuda_runtime.h>
#include <cuda_bf16.h>

#define NN 50000
#define EE 1000000
#define IN_DIM 128
#define HID 64
#define NL 4
#define SCAN_B 196   // ceil(NN/256)

// ---------------- host-side stream/events (created pre-main) ------------------
struct HxStreams {
    cudaStream_t s1;
    cudaEvent_t ev_fork, ev_join;
    HxStreams() {
        cudaStreamCreateWithFlags(&s1, cudaStreamNonBlocking);
        cudaEventCreateWithFlags(&ev_fork, cudaEventDisableTiming);
        cudaEventCreateWithFlags(&ev_join, cudaEventDisableTiming);
    }
};
static HxStreams g_hx;

// ---------------- scratch (static device globals; no allocation) -------------
__device__ float    g_h[NN * HID];     // node features (residual-applied)
__device__ float    g_hp[NN * HID];    // pre-BN layer output
__device__ float    g_A[NN * HID];
__device__ float    g_E[NN * HID];
__device__ unsigned g_BD[NN * 64];     // interleaved: even word = D pack, odd = B pack
__device__ int      g_deg[NN];
__device__ int      g_offs[NN + 1];
__device__ int      g_cursor[NN];
__device__ int      g_csr[EE];
__device__ float    g_stats[NL][2 * HID];
__device__ int      g_bpre[256];
// pre-split weights, quad layout: row c (64 words), quad(ks,tig) XOR-swizzled by c&1,
// quad = [hi_kpa, lo_kpa, hi_kpb, lo_kpb], kpa=ks*8+tig, kpb=kpa+4
__device__ unsigned g_W[NL * 256 * 64];

__device__ __forceinline__ unsigned pack_bf16x2(float a, float b) {
    __nv_bfloat162 h = __floats2bfloat162_rn(a, b);
    return *reinterpret_cast<unsigned*>(&h);
}
__device__ __forceinline__ float2 unpack_bf16x2(unsigned u) {
    __nv_bfloat162 h = *reinterpret_cast<__nv_bfloat162*>(&u);
    return __bfloat1622float2(h);
}
__device__ __forceinline__ float sigmoid_fast(float x) {
    float t;
    asm("tanh.approx.f32 %0, %1;" : "=f"(t) : "f"(0.5f * x));
    return fmaf(t, 0.5f, 0.5f);
}
__device__ __forceinline__ void split_pair(float x0, float x1,
                                           unsigned& hw, unsigned& lw) {
    __nv_bfloat16 h0 = __float2bfloat16(x0);
    __nv_bfloat16 h1 = __float2bfloat16(x1);
    float r0 = x0 - __bfloat162float(h0);
    float r1 = x1 - __bfloat162float(h1);
    __nv_bfloat16 l0 = __float2bfloat16(r0);
    __nv_bfloat16 l1 = __float2bfloat16(r1);
    hw = (unsigned)__bfloat16_as_ushort(h0) | ((unsigned)__bfloat16_as_ushort(h1) << 16);
    lw = (unsigned)__bfloat16_as_ushort(l0) | ((unsigned)__bfloat16_as_ushort(l1) << 16);
}
__device__ __forceinline__ void mma_bf16(float* d, const unsigned* a, const unsigned* b) {
    asm("mma.sync.aligned.m16n8k16.row.col.f32.bf16.bf16.f32 "
        "{%0,%1,%2,%3}, {%4,%5,%6,%7}, {%8,%9}, {%0,%1,%2,%3};"
        : "+f"(d[0]), "+f"(d[1]), "+f"(d[2]), "+f"(d[3])
        : "r"(a[0]), "r"(a[1]), "r"(a[2]), "r"(a[3]), "r"(b[0]), "r"(b[1]));
}
// quad slot (word offset within 64-word row) for pair index kp, row/col parity p
__device__ __forceinline__ int quad_off(int kp, int p) {
    int tig = kp & 3, hf = (kp >> 2) & 1, ks = kp >> 3;
    int q = ks * 4 + tig;
    return (q ^ (p << 2)) * 4 + hf * 2;
}

// ---------------- s0 head: weight split (quad layout) + stats clear -----------
__global__ void k_wsplit(const float* __restrict__ Aw, const float* __restrict__ Bw,
                         const float* __restrict__ Dw, const float* __restrict__ Ew) {
    int b = blockIdx.x, t = threadIdx.x;
    int i = b * 256 + t;
    if (i < NL * 2 * HID) ((float*)g_stats)[i] = 0.f;
    for (int idx = t; idx < 256 * 32; idx += 256) {
        int c = idx >> 5, kp = idx & 31;
        int sel = c >> 6, cc = c & 63;
        const float* W = (sel == 0) ? Aw : (sel == 1) ? Bw : (sel == 2) ? Dw : Ew;
        float w0 = W[b * HID * HID + (2 * kp) * HID + cc];
        float w1 = W[b * HID * HID + (2 * kp + 1) * HID + cc];
        unsigned hw, lw;
        split_pair(w0, w1, hw, lw);
        *(uint2*)&g_W[b * 16384 + c * 64 + quad_off(kp, c & 1)] = make_uint2(hw, lw);
    }
}

// ---------------- s1 chain: CSR build -----------------------------------------
__global__ void k_cleardeg() {
    int i = blockIdx.x * blockDim.x + threadIdx.x;
    if (i < NN) g_deg[i] = 0;
}

__global__ void k_hist(const int* __restrict__ ei) {
    int e = (blockIdx.x * blockDim.x + threadIdx.x) * 4;
    if (e < EE) {
        int4 d4 = *(const int4*)&ei[EE + e];
        if (d4.x >= 0 && d4.x < NN) atomicAdd(&g_deg[d4.x], 1);
        if (d4.y >= 0 && d4.y < NN) atomicAdd(&g_deg[d4.y], 1);
        if (d4.z >= 0 && d4.z < NN) atomicAdd(&g_deg[d4.z], 1);
        if (d4.w >= 0 && d4.w < NN) atomicAdd(&g_deg[d4.w], 1);
    }
}

__global__ void k_scan1() {
    __shared__ int sums[224];
    __shared__ int ws[8];
    int t = threadIdx.x, lane = t & 31, w = t >> 5;
    for (int c = t; c < 224; c += 256) sums[c] = 0;
    __syncthreads();
    for (int c = w; c < SCAN_B; c += 8) {
        int s = 0;
        #pragma unroll
        for (int i = 0; i < 8; i++) {
            int idx = c * 256 + i * 32 + lane;
            s += (idx < NN) ? g_deg[idx] : 0;
        }
        #pragma unroll
        for (int o = 16; o; o >>= 1) s += __shfl_down_sync(0xffffffffu, s, o);
        if (lane == 0) sums[c] = s;
    }
    __syncthreads();
    int v = (t < SCAN_B) ? sums[t] : 0;
    int x = v;
    #pragma unroll
    for (int o = 1; o < 32; o <<= 1) {
        int y = __shfl_up_sync(0xffffffffu, x, o);
        if (lane >= o) x += y;
    }
    if (lane == 31) ws[w] = x;
    __syncthreads();
    if (t < 8) {
        int q = ws[t];
        #pragma unroll
        for (int o = 1; o < 8; o <<= 1) {
            int y = __shfl_up_sync(0xffu, q, o);
            if (t >= o) q += y;
        }
        ws[t] = q;
    }
    __syncthreads();
    int incl = x + (w ? ws[w - 1] : 0);
    g_bpre[t] = incl - v;
}

__global__ void k_offs() {
    __shared__ int ws[8];
    int t = threadIdx.x, b = blockIdx.x;
    int i = b * 256 + t;
    int v = (i < NN) ? g_deg[i] : 0;
    int lane = t & 31, wid = t >> 5;
    int x = v;
    #pragma unroll
    for (int o = 1; o < 32; o <<= 1) {
        int y = __shfl_up_sync(0xffffffffu, x, o);
        if (lane >= o) x += y;
    }
    if (lane == 31) ws[wid] = x;
    __syncthreads();
    if (t < 8) {
        int w = ws[t];
        #pragma unroll
        for (int o = 1; o < 8; o <<= 1) {
            int y = __shfl_up_sync(0xffu, w, o);
            if (t >= o) w += y;
        }
        ws[t] = w;
    }
    __syncthreads();
    int incl = x + (wid ? ws[wid - 1] : 0);
    int base = g_bpre[b];
    if (i < NN) {
        g_offs[i + 1] = base + incl;
        g_cursor[i]   = base + incl - v;
    }
    if (i == 0) g_offs[0] = 0;
}

__global__ void k_scatter(const int* __restrict__ ei) {
    int e = (blockIdx.x * blockDim.x + threadIdx.x) * 4;
    if (e < EE) {
        int4 s4 = *(const int4*)&ei[e];
        int4 d4 = *(const int4*)&ei[EE + e];
        if (d4.x >= 0 && d4.x < NN) {
            int pos = atomicAdd(&g_cursor[d4.x], 1);
            if (pos >= 0 && pos < EE) g_csr[pos] = s4.x;
        }
        if (d4.y >= 0 && d4.y < NN) {
            int pos = atomicAdd(&g_cursor[d4.y], 1);
            if (pos >= 0 && pos < EE) g_csr[pos] = s4.y;
        }
        if (d4.z >= 0 && d4.z < NN) {
            int pos = atomicAdd(&g_cursor[d4.z], 1);
            if (pos >= 0 && pos < EE) g_csr[pos] = s4.z;
        }
        if (d4.w >= 0 && d4.w < NN) {
            int pos = atomicAdd(&g_cursor[d4.w], 1);
            if (pos >= 0 && pos < EE) g_csr[pos] = s4.w;
        }
    }
}

// ---------------- embed: bf16 MMA 3-term (old split layout, unchanged) --------
__global__ __launch_bounds__(256) void k_embed(const float* __restrict__ X,
                                               const float* __restrict__ W,
                                               const float* __restrict__ bias) {
    __shared__ unsigned Xh[64 * 32], Xl[64 * 32];
    __shared__ unsigned Wh[64 * 32], Wl[64 * 32];
    int t = threadIdx.x;
    int m0 = blockIdx.x * 64;
    int lane = t & 31, w = t >> 5;
    int g = lane >> 2, tig = lane & 3;
    int mt = w & 3, ns = w >> 2;
    int r0 = mt * 16 + g, r1 = r0 + 8;

    float acc[4][4];
    #pragma unroll
    for (int i = 0; i < 4; i++)
        #pragma unroll
        for (int j = 0; j < 4; j++) acc[i][j] = 0.f;

    #pragma unroll
    for (int kc = 0; kc < 2; kc++) {
        for (int idx = t; idx < 64 * 16; idx += 256) {
            int r = idx >> 4, c4 = (idx & 15) * 4;
            int m = m0 + r;
            float4 v = make_float4(0.f, 0.f, 0.f, 0.f);
            if (m < NN) v = *(const float4*)&X[m * IN_DIM + kc * 64 + c4];
            int kp0 = c4 >> 1, swz = (r & 7) << 2;
            unsigned hw, lw;
            split_pair(v.x, v.y, hw, lw);
            Xh[r * 32 + (kp0 ^ swz)] = hw;
            Xl[r * 32 + (kp0 ^ swz)] = lw;
            split_pair(v.z, v.w, hw, lw);
            Xh[r * 32 + ((kp0 + 1) ^ swz)] = hw;
            Xl[r * 32 + ((kp0 + 1) ^ swz)] = lw;
        }
        for (int idx = t; idx < 32 * 64; idx += 256) {
            int kp = idx >> 6, c = idx & 63;
            float w0 = W[(kc * 64 + 2 * kp) * HID + c];
            float w1 = W[(kc * 64 + 2 * kp + 1) * HID + c];
            unsigned hw, lw;
            split_pair(w0, w1, hw, lw);
            int s = c * 32 + (kp ^ ((c & 7) << 2));
            Wh[s] = hw;
            Wl[s] = lw;
        }
        __syncthreads();

        int swa0 = (r0 & 7) << 2, swa1 = (r1 & 7) << 2;
        #pragma unroll
        for (int ks = 0; ks < 4; ks++) {
            int kpa = ks * 8 + tig, kpb = kpa + 4;
            unsigned ah[4], al[4];
            int s0 = r0 * 32 + (kpa ^ swa0), s1 = r1 * 32 + (kpa ^ swa1);
            int s2 = r0 * 32 + (kpb ^ swa0), s3 = r1 * 32 + (kpb ^ swa1);
            ah[0] = Xh[s0]; ah[1] = Xh[s1]; ah[2] = Xh[s2]; ah[3] = Xh[s3];
            al[0] = Xl[s0]; al[1] = Xl[s1]; al[2] = Xl[s2]; al[3] = Xl[s3];
            #pragma unroll
            for (int nt = 0; nt < 4; nt++) {
                int c = ns * 32 + nt * 8 + g;
                int swc = (c & 7) << 2;
                int sb0 = c * 32 + (kpa ^ swc);
                int sb1 = c * 32 + (kpb ^ swc);
                unsigned bh[2] = {Wh[sb0], Wh[sb1]};
                unsigned bl[2] = {Wl[sb0], Wl[sb1]};
                mma_bf16(acc[nt], ah, bh);
                mma_bf16(acc[nt], al, bh);
                mma_bf16(acc[nt], ah, bl);
            }
        }
        __syncthreads();
    }

    int mra = m0 + mt * 16 + g, mrb = mra + 8;
    #pragma unroll
    for (int nt = 0; nt < 4; nt++) {
        int cc = ns * 32 + nt * 8 + 2 * tig;
        float b0 = bias[cc], b1 = bias[cc + 1];
        if (mra < NN)
            *(float2*)&g_h[mra * HID + cc] = make_float2(acc[nt][0] + b0, acc[nt][1] + b1);
        if (mrb < NN)
            *(float2*)&g_h[mrb * HID + cc] = make_float2(acc[nt][2] + b0, acc[nt][3] + b1);
    }
}

// ---------------- layer linears: quad-layout bf16 MMA (LDS.128 fragments) -----
__global__ __launch_bounds__(256) void k_abde(
    const float* __restrict__ Ab, const float* __restrict__ Bb,
    const float* __restrict__ Db, const float* __restrict__ Eb,
    const float* __restrict__ pg, const float* __restrict__ pb,
    int l) {
    __shared__ unsigned Xs[64 * 64];    // 16KB: row r, quad layout, parity r&1
    __shared__ unsigned Ws[128 * 64];   // 32KB: row c, quad layout, parity c&1
    int t = threadIdx.x;
    int m0 = blockIdx.x * 64;
    const float invN = 1.f / (float)NN;

    // ---- stage X: fused BN of prev layer, quad layout -----------------------
    for (int idx = t; idx < 64 * 16; idx += 256) {
        int r = idx >> 4, c4 = (idx & 15) * 4;
        int m = m0 + r;
        float4 v = make_float4(0.f, 0.f, 0.f, 0.f);
        if (m < NN) {
            v = *(const float4*)&g_h[m * HID + c4];
            if (l > 0) {
                const float* st = g_stats[l - 1];
                float4 hp = *(const float4*)&g_hp[m * HID + c4];
                #pragma unroll
                for (int j = 0; j < 4; j++) {
                    int c = c4 + j;
                    float mu  = st[c] * invN;
                    float var = st[HID + c] * invN - mu * mu;
                    float hpv = (j == 0) ? hp.x : (j == 1) ? hp.y : (j == 2) ? hp.z : hp.w;
                    float xn  = (hpv - mu) * rsqrtf(var + 1e-5f);
                    float vv  = fmaxf(pg[c] * xn + pb[c], 0.f);
                    if (j == 0) v.x += vv; else if (j == 1) v.y += vv;
                    else if (j == 2) v.z += vv; else v.w += vv;
                }
                *(float4*)&g_h[m * HID + c4] = v;
            }
        }
        int kp0 = c4 >> 1, p = r & 1;
        unsigned hw, lw;
        split_pair(v.x, v.y, hw, lw);
        *(uint2*)&Xs[r * 64 + quad_off(kp0, p)] = make_uint2(hw, lw);
        split_pair(v.z, v.w, hw, lw);
        *(uint2*)&Xs[r * 64 + quad_off(kp0 + 1, p)] = make_uint2(hw, lw);
    }

    int lane = t & 31, w = t >> 5;
    int g = lane >> 2, tig = lane & 3;
    int mt = w & 3, ns = w >> 2;
    int r0 = mt * 16 + g, r1 = r0 + 8;

    #pragma unroll
    for (int half = 0; half < 2; half++) {
        // stage W half: straight uint4 copy of 32KB (layout pre-built globally)
        {
            const uint4* src = (const uint4*)(g_W + l * 16384 + half * 8192);
            uint4* dst = (uint4*)Ws;
            #pragma unroll
            for (int j = 0; j < 8; j++)
                dst[t + j * 256] = src[t + j * 256];
        }
        __syncthreads();

        float acc[8][4];
        #pragma unroll
        for (int i = 0; i < 8; i++)
            #pragma unroll
            for (int j = 0; j < 4; j++) acc[i][j] = 0.f;

        int pA = r0 & 1;   // r1 = r0+8 -> same parity
        #pragma unroll
        for (int ks = 0; ks < 4; ks++) {
            int qA = ((ks * 4 + tig) ^ (pA << 2)) * 4;
            uint4 a0 = *(const uint4*)&Xs[r0 * 64 + qA];
            uint4 a1 = *(const uint4*)&Xs[r1 * 64 + qA];
            unsigned ah[4] = {a0.x, a1.x, a0.z, a1.z};
            unsigned al[4] = {a0.y, a1.y, a0.w, a1.w};
            #pragma unroll
            for (int nt = 0; nt < 8; nt++) {
                int c = ns * 64 + nt * 8 + g;
                int qB = ((ks * 4 + tig) ^ ((c & 1) << 2)) * 4;
                uint4 b = *(const uint4*)&Ws[c * 64 + qB];
                unsigned bh[2] = {b.x, b.z};
                unsigned bl[2] = {b.y, b.w};
                mma_bf16(acc[nt], ah, bh);
                mma_bf16(acc[nt], al, bh);
                mma_bf16(acc[nt], ah, bl);
            }
        }

        int sel = half * 2 + ns;
        const float* bp = (sel == 0) ? Ab : (sel == 1) ? Bb : (sel == 2) ? Db : Eb;
        int mra = m0 + mt * 16 + g, mrb = mra + 8;
        if (sel == 0 || sel == 3) {
            float* Y = (sel == 0) ? g_A : g_E;
            #pragma unroll
            for (int nt = 0; nt < 8; nt++) {
                int cc = nt * 8 + 2 * tig;
                float b0v = bp[cc], b1v = bp[cc + 1];
                if (mra < NN)
                    *(float2*)&Y[mra * HID + cc] = make_float2(acc[nt][0] + b0v, acc[nt][1] + b1v);
                if (mrb < NN)
                    *(float2*)&Y[mrb * HID + cc] = make_float2(acc[nt][2] + b0v, acc[nt][3] + b1v);
            }
        } else {
            int boff = (sel == 1) ? 1 : 0;
            #pragma unroll
            for (int nt = 0; nt < 8; nt++) {
                int cc = nt * 8 + 2 * tig;
                float b0v = bp[cc], b1v = bp[cc + 1];
                if (mra < NN)
                    g_BD[mra * 64 + cc + boff] = pack_bf16x2(acc[nt][0] + b0v, acc[nt][1] + b1v);
                if (mrb < NN)
                    g_BD[mrb * 64 + cc + boff] = pack_bf16x2(acc[nt][2] + b0v, acc[nt][3] + b1v);
            }
        }
        __syncthreads();
    }
}

// ---------------- edge aggregation + fused BN stats (8-edge unrolled) ---------
__global__ __launch_bounds__(256) void k_agg(int l) {
    __shared__ float red_s[8][64], red_q[8][64];
    int w = threadIdx.x >> 5, lane = threadIdx.x & 31;
    int base = (blockIdx.x * 8 + w) * 4;
    float sx = 0.f, sy = 0.f, qx = 0.f, qy = 0.f;
    #pragma unroll 1
    for (int i = 0; i < 4; i++) {
        int gw = base + i;
        if (gw >= NN) break;
        int s0 = g_offs[gw], s1 = g_offs[gw + 1];
        int off = gw * HID + lane * 2;
        float2 el = *(const float2*)&g_E[off];
        float nx = 0.f, ny = 0.f, dx = 0.f, dy = 0.f;
        int k = s0;
        for (; k + 7 < s1; k += 8) {
            int sidx[8];
            uint2 v[8];
            #pragma unroll
            for (int j = 0; j < 8; j++) sidx[j] = g_csr[k + j];
            #pragma unroll
            for (int j = 0; j < 8; j++) v[j] = *(const uint2*)&g_BD[sidx[j] * 64 + lane * 2];
            #pragma unroll
            for (int j = 0; j < 8; j++) {
                float2 d = unpack_bf16x2(v[j].x), b = unpack_bf16x2(v[j].y);
                float gx = sigmoid_fast(d.x + el.x);
                float gy = sigmoid_fast(d.y + el.y);
                nx += gx * b.x; ny += gy * b.y;
                dx += gx;       dy += gy;
            }
        }
        for (; k + 3 < s1; k += 4) {
            int sidx[4];
            uint2 v[4];
            #pragma unroll
            for (int j = 0; j < 4; j++) sidx[j] = g_csr[k + j];
            #pragma unroll
            for (int j = 0; j < 4; j++) v[j] = *(const uint2*)&g_BD[sidx[j] * 64 + lane * 2];
            #pragma unroll
            for (int j = 0; j < 4; j++) {
                float2 d = unpack_bf16x2(v[j].x), b = unpack_bf16x2(v[j].y);
                float gx = sigmoid_fast(d.x + el.x);
                float gy = sigmoid_fast(d.y + el.y);
                nx += gx * b.x; ny += gy * b.y;
                dx += gx;       dy += gy;
            }
        }
        for (; k < s1; k++) {
            int sa = g_csr[k];
            uint2 va = *(const uint2*)&g_BD[sa * 64 + lane * 2];
            float2 d = unpack_bf16x2(va.x), b = unpack_bf16x2(va.y);
            float gx = sigmoid_fast(d.x + el.x);
            float gy = sigmoid_fast(d.y + el.y);
            nx += gx * b.x; ny += gy * b.y;
            dx += gx;       dy += gy;
        }
        float2 aa = *(const float2*)&g_A[off];
        float ox = aa.x + nx / (dx + 1e-6f);
        float oy = aa.y + ny / (dy + 1e-6f);
        *(float2*)&g_hp[off] = make_float2(ox, oy);
        sx += ox; sy += oy; qx += ox * ox; qy += oy * oy;
    }
    red_s[w][lane * 2] = sx;  red_s[w][lane * 2 + 1] = sy;
    red_q[w][lane * 2] = qx;  red_q[w][lane * 2 + 1] = qy;
    __syncthreads();
    int t = threadIdx.x;
    if (t < 64) {
        float s = 0.f, q = 0.f;
        #pragma unroll
        for (int ww = 0; ww < 8; ww++) { s += red_s[ww][t]; q += red_q[ww][t]; }
        atomicAdd(&g_stats[l][t], s);
        atomicAdd(&g_stats[l][HID + t], q);
    }
}

// ---------------- final BN/ReLU/residual -> d_out -----------------------------
__global__ __launch_bounds__(256) void k_bn_final(const float* __restrict__ gamma,
                                                  const float* __restrict__ beta,
                                                  float* __restrict__ out) {
    int idx = blockIdx.x * blockDim.x + threadIdx.x;
    if (idx >= NN * HID) return;
    int c = idx & 63;
    const float* st = g_stats[NL - 1];
    const float invN = 1.f / (float)NN;
    float mu  = st[c] * invN;
    float var = st[HID + c] * invN - mu * mu;
    float xn = (g_hp[idx] - mu) * rsqrtf(var + 1e-5f);
    float v = fmaxf(gamma[c] * xn + beta[c], 0.f);
    out[idx] = g_h[idx] + v;
}

// ---------------- launch ------------------------------------------------------
extern "C" void kernel_launch(void* const* d_in, const int* in_sizes, int n_in,
                              void* d_out, int out_size) {
    const float* feature = (const float*)d_in[0];
    const int*   ei      = (const int*)d_in[1];     // int32 (JAX x64 disabled)
    const float* emb_w   = (const float*)d_in[2];
    const float* emb_b   = (const float*)d_in[3];
    const float* Aw      = (const float*)d_in[4];
    const float* Ab      = (const float*)d_in[5];
    const float* Bw      = (const float*)d_in[6];
    const float* Bb      = (const float*)d_in[7];
    const float* Dw      = (const float*)d_in[8];
    const float* Db      = (const float*)d_in[9];
    const float* Ew      = (const float*)d_in[10];
    const float* Eb      = (const float*)d_in[11];
    const float* gamma   = (const float*)d_in[12];
    const float* beta    = (const float*)d_in[13];
    float* out = (float*)d_out;

    // fork: CSR build on side stream, GEMM chain on origin stream
    cudaEventRecord(g_hx.ev_fork, 0);
    cudaStreamWaitEvent(g_hx.s1, g_hx.ev_fork, 0);

    // s1: CSR build
    k_cleardeg<<<(NN + 255) / 256, 256, 0, g_hx.s1>>>();
    k_hist<<<(EE / 4 + 255) / 256, 256, 0, g_hx.s1>>>(ei);
    k_scan1<<<1, 256, 0, g_hx.s1>>>();
    k_offs<<<SCAN_B, 256, 0, g_hx.s1>>>();
    k_scatter<<<(EE / 4 + 255) / 256, 256, 0, g_hx.s1>>>(ei);
    cudaEventRecord(g_hx.ev_join, g_hx.s1);

    // s0: weight split -> embed -> abde(l=0)
    k_wsplit<<<NL, 256>>>(Aw, Bw, Dw, Ew);
    k_embed<<<(NN + 63) / 64, 256>>>(feature, emb_w, emb_b);
    k_abde<<<(NN + 63) / 64, 256>>>(Ab, Bb, Db, Eb, gamma, beta, 0);

    // join: agg needs CSR
    cudaStreamWaitEvent(0, g_hx.ev_join, 0);
    k_agg<<<(NN + 31) / 32, 256>>>(0);

    for (int l = 1; l < NL; l++) {
        const float* pg = gamma + (l - 1) * HID;
        const float* pb = beta  + (l - 1) * HID;
        k_abde<<<(NN + 63) / 64, 256>>>(
            Ab + l * HID, Bb + l * HID, Db + l * HID, Eb + l * HID,
            pg, pb, l);
        k_agg<<<(NN + 31) / 32, 256>>>(l);
    }
    k_bn_final<<<(NN * HID + 255) / 256, 256>>>(gamma + (NL - 1) * HID,
                                                beta + (NL - 1) * HID, out);
}

// round 14
// speedup vs baseline: 1.0666x; 1.0666x over previous
#include <cuda_runtime.h>
#include <cuda_bf16.h>

#define NN 50000
#define EE 1000000
#define IN_DIM 128
#define HID 64
#define NL 4
#define SCAN_B 196   // ceil(NN/256)

// ---------------- host-side stream/events (created pre-main) ------------------
struct HxStreams {
    cudaStream_t s1;
    cudaEvent_t ev_fork, ev_join;
    HxStreams() {
        cudaStreamCreateWithFlags(&s1, cudaStreamNonBlocking);
        cudaEventCreateWithFlags(&ev_fork, cudaEventDisableTiming);
        cudaEventCreateWithFlags(&ev_join, cudaEventDisableTiming);
    }
};
static HxStreams g_hx;

// ---------------- scratch (static device globals; no allocation) -------------
__device__ float    g_h[NN * HID];     // node features (residual-applied)
__device__ float    g_hp[NN * HID];    // pre-BN layer output
__device__ float    g_A[NN * HID];
__device__ float    g_E[NN * HID];
__device__ unsigned g_BD[NN * 64];     // interleaved: even word = D pack, odd = B pack
__device__ int      g_deg[NN];
__device__ int      g_offs[NN + 1];
__device__ int      g_cursor[NN];
__device__ int      g_csr[EE];
__device__ float    g_stats[NL][2 * HID];
__device__ int      g_bpre[256];
// pre-split weights, swizzled smem layout: [layer][c*32 + (kp ^ ((c&7)<<2))]
__device__ unsigned g_Wh[NL * 256 * 32];
__device__ unsigned g_Wl[NL * 256 * 32];

__device__ __forceinline__ unsigned pack_bf16x2(float a, float b) {
    __nv_bfloat162 h = __floats2bfloat162_rn(a, b);
    return *reinterpret_cast<unsigned*>(&h);
}
__device__ __forceinline__ float2 unpack_bf16x2(unsigned u) {
    __nv_bfloat162 h = *reinterpret_cast<__nv_bfloat162*>(&u);
    return __bfloat1622float2(h);
}
__device__ __forceinline__ float sigmoid_fast(float x) {
    float t;
    asm("tanh.approx.f32 %0, %1;" : "=f"(t) : "f"(0.5f * x));
    return fmaf(t, 0.5f, 0.5f);
}
__device__ __forceinline__ void split_pair(float x0, float x1,
                                           unsigned& hw, unsigned& lw) {
    __nv_bfloat16 h0 = __float2bfloat16(x0);
    __nv_bfloat16 h1 = __float2bfloat16(x1);
    float r0 = x0 - __bfloat162float(h0);
    float r1 = x1 - __bfloat162float(h1);
    __nv_bfloat16 l0 = __float2bfloat16(r0);
    __nv_bfloat16 l1 = __float2bfloat16(r1);
    hw = (unsigned)__bfloat16_as_ushort(h0) | ((unsigned)__bfloat16_as_ushort(h1) << 16);
    lw = (unsigned)__bfloat16_as_ushort(l0) | ((unsigned)__bfloat16_as_ushort(l1) << 16);
}
__device__ __forceinline__ void mma_bf16(float* d, const unsigned* a, const unsigned* b) {
    asm("mma.sync.aligned.m16n8k16.row.col.f32.bf16.bf16.f32 "
        "{%0,%1,%2,%3}, {%4,%5,%6,%7}, {%8,%9}, {%0,%1,%2,%3};"
        : "+f"(d[0]), "+f"(d[1]), "+f"(d[2]), "+f"(d[3])
        : "r"(a[0]), "r"(a[1]), "r"(a[2]), "r"(a[3]), "r"(b[0]), "r"(b[1]));
}

// ---------------- s0 head: weight split + stats clear -------------------------
__global__ void k_wsplit(const float* __restrict__ Aw, const float* __restrict__ Bw,
                         const float* __restrict__ Dw, const float* __restrict__ Ew) {
    int b = blockIdx.x, t = threadIdx.x;
    int i = b * 256 + t;
    if (i < NL * 2 * HID) ((float*)g_stats)[i] = 0.f;
    for (int idx = t; idx < 256 * 32; idx += 256) {
        int c = idx >> 5, kp = idx & 31;
        int sel = c >> 6, cc = c & 63;
        const float* W = (sel == 0) ? Aw : (sel == 1) ? Bw : (sel == 2) ? Dw : Ew;
        float w0 = W[b * HID * HID + (2 * kp) * HID + cc];
        float w1 = W[b * HID * HID + (2 * kp + 1) * HID + cc];
        unsigned hw, lw;
        split_pair(w0, w1, hw, lw);
        int s = b * 8192 + c * 32 + (kp ^ ((c & 7) << 2));
        g_Wh[s] = hw;
        g_Wl[s] = lw;
    }
}

// ---------------- s1 chain: CSR build -----------------------------------------
__global__ void k_cleardeg() {
    int i = blockIdx.x * blockDim.x + threadIdx.x;
    if (i < NN) g_deg[i] = 0;
}

__global__ void k_hist(const int* __restrict__ ei) {
    int e = (blockIdx.x * blockDim.x + threadIdx.x) * 4;
    if (e < EE) {
        int4 d4 = *(const int4*)&ei[EE + e];
        if (d4.x >= 0 && d4.x < NN) atomicAdd(&g_deg[d4.x], 1);
        if (d4.y >= 0 && d4.y < NN) atomicAdd(&g_deg[d4.y], 1);
        if (d4.z >= 0 && d4.z < NN) atomicAdd(&g_deg[d4.z], 1);
        if (d4.w >= 0 && d4.w < NN) atomicAdd(&g_deg[d4.w], 1);
    }
}

__global__ void k_scan1() {
    __shared__ int sums[224];
    __shared__ int ws[8];
    int t = threadIdx.x, lane = t & 31, w = t >> 5;
    for (int c = t; c < 224; c += 256) sums[c] = 0;
    __syncthreads();
    for (int c = w; c < SCAN_B; c += 8) {
        int s = 0;
        #pragma unroll
        for (int i = 0; i < 8; i++) {
            int idx = c * 256 + i * 32 + lane;
            s += (idx < NN) ? g_deg[idx] : 0;
        }
        #pragma unroll
        for (int o = 16; o; o >>= 1) s += __shfl_down_sync(0xffffffffu, s, o);
        if (lane == 0) sums[c] = s;
    }
    __syncthreads();
    int v = (t < SCAN_B) ? sums[t] : 0;
    int x = v;
    #pragma unroll
    for (int o = 1; o < 32; o <<= 1) {
        int y = __shfl_up_sync(0xffffffffu, x, o);
        if (lane >= o) x += y;
    }
    if (lane == 31) ws[w] = x;
    __syncthreads();
    if (t < 8) {
        int q = ws[t];
        #pragma unroll
        for (int o = 1; o < 8; o <<= 1) {
            int y = __shfl_up_sync(0xffu, q, o);
            if (t >= o) q += y;
        }
        ws[t] = q;
    }
    __syncthreads();
    int incl = x + (w ? ws[w - 1] : 0);
    g_bpre[t] = incl - v;
}

__global__ void k_offs() {
    __shared__ int ws[8];
    int t = threadIdx.x, b = blockIdx.x;
    int i = b * 256 + t;
    int v = (i < NN) ? g_deg[i] : 0;
    int lane = t & 31, wid = t >> 5;
    int x = v;
    #pragma unroll
    for (int o = 1; o < 32; o <<= 1) {
        int y = __shfl_up_sync(0xffffffffu, x, o);
        if (lane >= o) x += y;
    }
    if (lane == 31) ws[wid] = x;
    __syncthreads();
    if (t < 8) {
        int w = ws[t];
        #pragma unroll
        for (int o = 1; o < 8; o <<= 1) {
            int y = __shfl_up_sync(0xffu, w, o);
            if (t >= o) w += y;
        }
        ws[t] = w;
    }
    __syncthreads();
    int incl = x + (wid ? ws[wid - 1] : 0);
    int base = g_bpre[b];
    if (i < NN) {
        g_offs[i + 1] = base + incl;
        g_cursor[i]   = base + incl - v;
    }
    if (i == 0) g_offs[0] = 0;
}

__global__ void k_scatter(const int* __restrict__ ei) {
    int e = (blockIdx.x * blockDim.x + threadIdx.x) * 4;
    if (e < EE) {
        int4 s4 = *(const int4*)&ei[e];
        int4 d4 = *(const int4*)&ei[EE + e];
        if (d4.x >= 0 && d4.x < NN) {
            int pos = atomicAdd(&g_cursor[d4.x], 1);
            if (pos >= 0 && pos < EE) g_csr[pos] = s4.x;
        }
        if (d4.y >= 0 && d4.y < NN) {
            int pos = atomicAdd(&g_cursor[d4.y], 1);
            if (pos >= 0 && pos < EE) g_csr[pos] = s4.y;
        }
        if (d4.z >= 0 && d4.z < NN) {
            int pos = atomicAdd(&g_cursor[d4.z], 1);
            if (pos >= 0 && pos < EE) g_csr[pos] = s4.z;
        }
        if (d4.w >= 0 && d4.w < NN) {
            int pos = atomicAdd(&g_cursor[d4.w], 1);
            if (pos >= 0 && pos < EE) g_csr[pos] = s4.w;
        }
    }
}

// ---------------- fused embed + abde(l=0) -------------------------------------
// Phase 1: embed GEMM (K=128, 2 chunks). Phase 2: fragments (+bias) -> g_h and
// directly into abde's X staging (kp = cc/2, swz = g). Phase 3: abde l=0 body.
__global__ __launch_bounds__(256) void k_embed_abde0(
    const float* __restrict__ X, const float* __restrict__ W,
    const float* __restrict__ bias,
    const float* __restrict__ Ab, const float* __restrict__ Bb,
    const float* __restrict__ Db, const float* __restrict__ Eb) {
    __shared__ unsigned Xh[64 * 32], Xl[64 * 32];
    __shared__ unsigned Wh[128 * 32], Wl[128 * 32];
    int t = threadIdx.x;
    int m0 = blockIdx.x * 64;
    int lane = t & 31, w = t >> 5;
    int g = lane >> 2, tig = lane & 3;
    int mt = w & 3, ns = w >> 2;
    int r0 = mt * 16 + g, r1 = r0 + 8;

    // ---- phase 1: embed mainloop -------------------------------------------
    float eacc[4][4];
    #pragma unroll
    for (int i = 0; i < 4; i++)
        #pragma unroll
        for (int j = 0; j < 4; j++) eacc[i][j] = 0.f;

    #pragma unroll
    for (int kc = 0; kc < 2; kc++) {
        for (int idx = t; idx < 64 * 16; idx += 256) {
            int r = idx >> 4, c4 = (idx & 15) * 4;
            int m = m0 + r;
            float4 v = make_float4(0.f, 0.f, 0.f, 0.f);
            if (m < NN) v = *(const float4*)&X[m * IN_DIM + kc * 64 + c4];
            int kp0 = c4 >> 1, swz = (r & 7) << 2;
            unsigned hw, lw;
            split_pair(v.x, v.y, hw, lw);
            Xh[r * 32 + (kp0 ^ swz)] = hw;
            Xl[r * 32 + (kp0 ^ swz)] = lw;
            split_pair(v.z, v.w, hw, lw);
            Xh[r * 32 + ((kp0 + 1) ^ swz)] = hw;
            Xl[r * 32 + ((kp0 + 1) ^ swz)] = lw;
        }
        for (int idx = t; idx < 32 * 64; idx += 256) {
            int kp = idx >> 6, c = idx & 63;
            float w0 = W[(kc * 64 + 2 * kp) * HID + c];
            float w1 = W[(kc * 64 + 2 * kp + 1) * HID + c];
            unsigned hw, lw;
            split_pair(w0, w1, hw, lw);
            int s = c * 32 + (kp ^ ((c & 7) << 2));
            Wh[s] = hw;
            Wl[s] = lw;
        }
        __syncthreads();

        int swa = g << 2;   // (r0&7) == (r1&7) == g
        #pragma unroll
        for (int ks = 0; ks < 4; ks++) {
            int kpa = ks * 8 + tig, kpb = kpa + 4;
            unsigned ah[4], al[4];
            int s0 = r0 * 32 + (kpa ^ swa), s1 = r1 * 32 + (kpa ^ swa);
            int s2 = r0 * 32 + (kpb ^ swa), s3 = r1 * 32 + (kpb ^ swa);
            ah[0] = Xh[s0]; ah[1] = Xh[s1]; ah[2] = Xh[s2]; ah[3] = Xh[s3];
            al[0] = Xl[s0]; al[1] = Xl[s1]; al[2] = Xl[s2]; al[3] = Xl[s3];
            #pragma unroll
            for (int nt = 0; nt < 4; nt++) {
                int c = ns * 32 + nt * 8 + g;
                int swc = (c & 7) << 2;
                int sb0 = c * 32 + (kpa ^ swc);
                int sb1 = c * 32 + (kpb ^ swc);
                unsigned bh[2] = {Wh[sb0], Wh[sb1]};
                unsigned bl[2] = {Wl[sb0], Wl[sb1]};
                mma_bf16(eacc[nt], ah, bh);
                mma_bf16(eacc[nt], al, bh);
                mma_bf16(eacc[nt], ah, bl);
            }
        }
        __syncthreads();
    }

    // ---- phase 2: write h + stage abde X directly from fragments -----------
    int mra = m0 + mt * 16 + g, mrb = mra + 8;
    {
        int swa = g << 2;
        #pragma unroll
        for (int nt = 0; nt < 4; nt++) {
            int cc = ns * 32 + nt * 8 + 2 * tig;
            float b0 = bias[cc], b1 = bias[cc + 1];
            float v0 = eacc[nt][0] + b0, v1 = eacc[nt][1] + b1;
            float v2 = eacc[nt][2] + b0, v3 = eacc[nt][3] + b1;
            if (mra < NN) *(float2*)&g_h[mra * HID + cc] = make_float2(v0, v1);
            else { v0 = 0.f; v1 = 0.f; }
            if (mrb < NN) *(float2*)&g_h[mrb * HID + cc] = make_float2(v2, v3);
            else { v2 = 0.f; v3 = 0.f; }
            int kp = cc >> 1;
            unsigned hw, lw;
            split_pair(v0, v1, hw, lw);
            Xh[r0 * 32 + (kp ^ swa)] = hw;
            Xl[r0 * 32 + (kp ^ swa)] = lw;
            split_pair(v2, v3, hw, lw);
            Xh[r1 * 32 + (kp ^ swa)] = hw;
            Xl[r1 * 32 + (kp ^ swa)] = lw;
        }
    }
    __syncthreads();

    // ---- phase 3: abde l=0 body --------------------------------------------
    #pragma unroll
    for (int half = 0; half < 2; half++) {
        {
            const uint4* srcH = (const uint4*)(g_Wh + half * 4096);
            const uint4* srcL = (const uint4*)(g_Wl + half * 4096);
            uint4* dstH = (uint4*)Wh;
            uint4* dstL = (uint4*)Wl;
            #pragma unroll
            for (int j = 0; j < 4; j++) {
                dstH[t + j * 256] = srcH[t + j * 256];
                dstL[t + j * 256] = srcL[t + j * 256];
            }
        }
        __syncthreads();

        float acc[8][4];
        #pragma unroll
        for (int i = 0; i < 8; i++)
            #pragma unroll
            for (int j = 0; j < 4; j++) acc[i][j] = 0.f;

        int swa = g << 2;
        #pragma unroll
        for (int ks = 0; ks < 4; ks++) {
            int kpa = ks * 8 + tig, kpb = kpa + 4;
            unsigned ah[4], al[4];
            int s0 = r0 * 32 + (kpa ^ swa), s1 = r1 * 32 + (kpa ^ swa);
            int s2 = r0 * 32 + (kpb ^ swa), s3 = r1 * 32 + (kpb ^ swa);
            ah[0] = Xh[s0]; ah[1] = Xh[s1]; ah[2] = Xh[s2]; ah[3] = Xh[s3];
            al[0] = Xl[s0]; al[1] = Xl[s1]; al[2] = Xl[s2]; al[3] = Xl[s3];
            #pragma unroll
            for (int nt = 0; nt < 8; nt++) {
                int c = ns * 64 + nt * 8 + g;
                int swc = (c & 7) << 2;
                int sb0 = c * 32 + (kpa ^ swc);
                int sb1 = c * 32 + (kpb ^ swc);
                unsigned bh[2] = {Wh[sb0], Wh[sb1]};
                unsigned bl[2] = {Wl[sb0], Wl[sb1]};
                mma_bf16(acc[nt], ah, bh);
                mma_bf16(acc[nt], al, bh);
                mma_bf16(acc[nt], ah, bl);
            }
        }

        int sel = half * 2 + ns;
        const float* bp = (sel == 0) ? Ab : (sel == 1) ? Bb : (sel == 2) ? Db : Eb;
        if (sel == 0 || sel == 3) {
            float* Y = (sel == 0) ? g_A : g_E;
            #pragma unroll
            for (int nt = 0; nt < 8; nt++) {
                int cc = nt * 8 + 2 * tig;
                float b0v = bp[cc], b1v = bp[cc + 1];
                if (mra < NN)
                    *(float2*)&Y[mra * HID + cc] = make_float2(acc[nt][0] + b0v, acc[nt][1] + b1v);
                if (mrb < NN)
                    *(float2*)&Y[mrb * HID + cc] = make_float2(acc[nt][2] + b0v, acc[nt][3] + b1v);
            }
        } else {
            int boff = (sel == 1) ? 1 : 0;
            #pragma unroll
            for (int nt = 0; nt < 8; nt++) {
                int cc = nt * 8 + 2 * tig;
                float b0v = bp[cc], b1v = bp[cc + 1];
                if (mra < NN)
                    g_BD[mra * 64 + cc + boff] = pack_bf16x2(acc[nt][0] + b0v, acc[nt][1] + b1v);
                if (mrb < NN)
                    g_BD[mrb * 64 + cc + boff] = pack_bf16x2(acc[nt][2] + b0v, acc[nt][3] + b1v);
            }
        }
        __syncthreads();
    }
}

// ---------------- layer linears: bf16 MMA, pre-split weights, fused BN -------
__global__ __launch_bounds__(256) void k_abde(
    const float* __restrict__ Ab, const float* __restrict__ Bb,
    const float* __restrict__ Db, const float* __restrict__ Eb,
    const float* __restrict__ pg, const float* __restrict__ pb,
    int l) {
    __shared__ unsigned Xh[64 * 32], Xl[64 * 32];
    __shared__ unsigned Wh[128 * 32], Wl[128 * 32];
    int t = threadIdx.x;
    int m0 = blockIdx.x * 64;
    const float invN = 1.f / (float)NN;

    for (int idx = t; idx < 64 * 16; idx += 256) {
        int r = idx >> 4, c4 = (idx & 15) * 4;
        int m = m0 + r;
        float4 v = make_float4(0.f, 0.f, 0.f, 0.f);
        if (m < NN) {
            v = *(const float4*)&g_h[m * HID + c4];
            const float* st = g_stats[l - 1];
            float4 hp = *(const float4*)&g_hp[m * HID + c4];
            #pragma unroll
            for (int j = 0; j < 4; j++) {
                int c = c4 + j;
                float mu  = st[c] * invN;
                float var = st[HID + c] * invN - mu * mu;
                float hpv = (j == 0) ? hp.x : (j == 1) ? hp.y : (j == 2) ? hp.z : hp.w;
                float xn  = (hpv - mu) * rsqrtf(var + 1e-5f);
                float vv  = fmaxf(pg[c] * xn + pb[c], 0.f);
                if (j == 0) v.x += vv; else if (j == 1) v.y += vv;
                else if (j == 2) v.z += vv; else v.w += vv;
            }
            *(float4*)&g_h[m * HID + c4] = v;
        }
        int kp0 = c4 >> 1;
        unsigned hw, lw;
        int swz = (r & 7) << 2;
        split_pair(v.x, v.y, hw, lw);
        Xh[r * 32 + (kp0 ^ swz)] = hw;
        Xl[r * 32 + (kp0 ^ swz)] = lw;
        split_pair(v.z, v.w, hw, lw);
        Xh[r * 32 + ((kp0 + 1) ^ swz)] = hw;
        Xl[r * 32 + ((kp0 + 1) ^ swz)] = lw;
    }

    int lane = t & 31, w = t >> 5;
    int g = lane >> 2, tig = lane & 3;
    int mt = w & 3, ns = w >> 2;
    int r0 = mt * 16 + g, r1 = r0 + 8;

    #pragma unroll
    for (int half = 0; half < 2; half++) {
        {
            const uint4* srcH = (const uint4*)(g_Wh + l * 8192 + half * 4096);
            const uint4* srcL = (const uint4*)(g_Wl + l * 8192 + half * 4096);
            uint4* dstH = (uint4*)Wh;
            uint4* dstL = (uint4*)Wl;
            #pragma unroll
            for (int j = 0; j < 4; j++) {
                dstH[t + j * 256] = srcH[t + j * 256];
                dstL[t + j * 256] = srcL[t + j * 256];
            }
        }
        __syncthreads();

        float acc[8][4];
        #pragma unroll
        for (int i = 0; i < 8; i++)
            #pragma unroll
            for (int j = 0; j < 4; j++) acc[i][j] = 0.f;

        int swa0 = (r0 & 7) << 2, swa1 = (r1 & 7) << 2;
        #pragma unroll
        for (int ks = 0; ks < 4; ks++) {
            int kb = ks * 8;
            int kpa = kb + tig, kpb = kb + tig + 4;
            unsigned ah[4], al[4];
            int s0 = r0 * 32 + (kpa ^ swa0), s1 = r1 * 32 + (kpa ^ swa1);
            int s2 = r0 * 32 + (kpb ^ swa0), s3 = r1 * 32 + (kpb ^ swa1);
            ah[0] = Xh[s0]; ah[1] = Xh[s1]; ah[2] = Xh[s2]; ah[3] = Xh[s3];
            al[0] = Xl[s0]; al[1] = Xl[s1]; al[2] = Xl[s2]; al[3] = Xl[s3];
            #pragma unroll
            for (int nt = 0; nt < 8; nt++) {
                int c = ns * 64 + nt * 8 + g;
                int swc = (c & 7) << 2;
                int sb0 = c * 32 + (kpa ^ swc);
                int sb1 = c * 32 + (kpb ^ swc);
                unsigned bh[2] = {Wh[sb0], Wh[sb1]};
                unsigned bl[2] = {Wl[sb0], Wl[sb1]};
                mma_bf16(acc[nt], ah, bh);
                mma_bf16(acc[nt], al, bh);
                mma_bf16(acc[nt], ah, bl);
            }
        }

        int sel = half * 2 + ns;
        const float* bp = (sel == 0) ? Ab : (sel == 1) ? Bb : (sel == 2) ? Db : Eb;
        int mra = m0 + mt * 16 + g, mrb = mra + 8;
        if (sel == 0 || sel == 3) {
            float* Y = (sel == 0) ? g_A : g_E;
            #pragma unroll
            for (int nt = 0; nt < 8; nt++) {
                int cc = nt * 8 + 2 * tig;
                float b0v = bp[cc], b1v = bp[cc + 1];
                if (mra < NN)
                    *(float2*)&Y[mra * HID + cc] = make_float2(acc[nt][0] + b0v, acc[nt][1] + b1v);
                if (mrb < NN)
                    *(float2*)&Y[mrb * HID + cc] = make_float2(acc[nt][2] + b0v, acc[nt][3] + b1v);
            }
        } else {
            int boff = (sel == 1) ? 1 : 0;
            #pragma unroll
            for (int nt = 0; nt < 8; nt++) {
                int cc = nt * 8 + 2 * tig;
                float b0v = bp[cc], b1v = bp[cc + 1];
                if (mra < NN)
                    g_BD[mra * 64 + cc + boff] = pack_bf16x2(acc[nt][0] + b0v, acc[nt][1] + b1v);
                if (mrb < NN)
                    g_BD[mrb * 64 + cc + boff] = pack_bf16x2(acc[nt][2] + b0v, acc[nt][3] + b1v);
            }
        }
        __syncthreads();
    }
}

// ---------------- edge aggregation + fused BN stats (8-edge unrolled) ---------
__global__ __launch_bounds__(256) void k_agg(int l) {
    __shared__ float red_s[8][64], red_q[8][64];
    int w = threadIdx.x >> 5, lane = threadIdx.x & 31;
    int base = (blockIdx.x * 8 + w) * 4;
    float sx = 0.f, sy = 0.f, qx = 0.f, qy = 0.f;
    #pragma unroll 1
    for (int i = 0; i < 4; i++) {
        int gw = base + i;
        if (gw >= NN) break;
        int s0 = g_offs[gw], s1 = g_offs[gw + 1];
        int off = gw * HID + lane * 2;
        float2 el = *(const float2*)&g_E[off];
        float nx = 0.f, ny = 0.f, dx = 0.f, dy = 0.f;
        int k = s0;
        for (; k + 7 < s1; k += 8) {
            int sidx[8];
            uint2 v[8];
            #pragma unroll
            for (int j = 0; j < 8; j++) sidx[j] = g_csr[k + j];
            #pragma unroll
            for (int j = 0; j < 8; j++) v[j] = *(const uint2*)&g_BD[sidx[j] * 64 + lane * 2];
            #pragma unroll
            for (int j = 0; j < 8; j++) {
                float2 d = unpack_bf16x2(v[j].x), b = unpack_bf16x2(v[j].y);
                float gx = sigmoid_fast(d.x + el.x);
                float gy = sigmoid_fast(d.y + el.y);
                nx += gx * b.x; ny += gy * b.y;
                dx += gx;       dy += gy;
            }
        }
        for (; k + 3 < s1; k += 4) {
            int sidx[4];
            uint2 v[4];
            #pragma unroll
            for (int j = 0; j < 4; j++) sidx[j] = g_csr[k + j];
            #pragma unroll
            for (int j = 0; j < 4; j++) v[j] = *(const uint2*)&g_BD[sidx[j] * 64 + lane * 2];
            #pragma unroll
            for (int j = 0; j < 4; j++) {
                float2 d = unpack_bf16x2(v[j].x), b = unpack_bf16x2(v[j].y);
                float gx = sigmoid_fast(d.x + el.x);
                float gy = sigmoid_fast(d.y + el.y);
                nx += gx * b.x; ny += gy * b.y;
                dx += gx;       dy += gy;
            }
        }
        for (; k < s1; k++) {
            int sa = g_csr[k];
            uint2 va = *(const uint2*)&g_BD[sa * 64 + lane * 2];
            float2 d = unpack_bf16x2(va.x), b = unpack_bf16x2(va.y);
            float gx = sigmoid_fast(d.x + el.x);
            float gy = sigmoid_fast(d.y + el.y);
            nx += gx * b.x; ny += gy * b.y;
            dx += gx;       dy += gy;
        }
        float2 aa = *(const float2*)&g_A[off];
        float ox = aa.x + nx / (dx + 1e-6f);
        float oy = aa.y + ny / (dy + 1e-6f);
        *(float2*)&g_hp[off] = make_float2(ox, oy);
        sx += ox; sy += oy; qx += ox * ox; qy += oy * oy;
    }
    red_s[w][lane * 2] = sx;  red_s[w][lane * 2 + 1] = sy;
    red_q[w][lane * 2] = qx;  red_q[w][lane * 2 + 1] = qy;
    __syncthreads();
    int t = threadIdx.x;
    if (t < 64) {
        float s = 0.f, q = 0.f;
        #pragma unroll
        for (int ww = 0; ww < 8; ww++) { s += red_s[ww][t]; q += red_q[ww][t]; }
        atomicAdd(&g_stats[l][t], s);
        atomicAdd(&g_stats[l][HID + t], q);
    }
}

// ---------------- final BN/ReLU/residual -> d_out -----------------------------
__global__ __launch_bounds__(256) void k_bn_final(const float* __restrict__ gamma,
                                                  const float* __restrict__ beta,
                                                  float* __restrict__ out) {
    int idx = blockIdx.x * blockDim.x + threadIdx.x;
    if (idx >= NN * HID) return;
    int c = idx & 63;
    const float* st = g_stats[NL - 1];
    const float invN = 1.f / (float)NN;
    float mu  = st[c] * invN;
    float var = st[HID + c] * invN - mu * mu;
    float xn = (g_hp[idx] - mu) * rsqrtf(var + 1e-5f);
    float v = fmaxf(gamma[c] * xn + beta[c], 0.f);
    out[idx] = g_h[idx] + v;
}

// ---------------- launch ------------------------------------------------------
extern "C" void kernel_launch(void* const* d_in, const int* in_sizes, int n_in,
                              void* d_out, int out_size) {
    const float* feature = (const float*)d_in[0];
    const int*   ei      = (const int*)d_in[1];     // int32 (JAX x64 disabled)
    const float* emb_w   = (const float*)d_in[2];
    const float* emb_b   = (const float*)d_in[3];
    const float* Aw      = (const float*)d_in[4];
    const float* Ab      = (const float*)d_in[5];
    const float* Bw      = (const float*)d_in[6];
    const float* Bb      = (const float*)d_in[7];
    const float* Dw      = (const float*)d_in[8];
    const float* Db      = (const float*)d_in[9];
    const float* Ew      = (const float*)d_in[10];
    const float* Eb      = (const float*)d_in[11];
    const float* gamma   = (const float*)d_in[12];
    const float* beta    = (const float*)d_in[13];
    float* out = (float*)d_out;

    // fork: CSR build on side stream, GEMM chain on origin stream
    cudaEventRecord(g_hx.ev_fork, 0);
    cudaStreamWaitEvent(g_hx.s1, g_hx.ev_fork, 0);

    // s1: CSR build
    k_cleardeg<<<(NN + 255) / 256, 256, 0, g_hx.s1>>>();
    k_hist<<<(EE / 4 + 255) / 256, 256, 0, g_hx.s1>>>(ei);
    k_scan1<<<1, 256, 0, g_hx.s1>>>();
    k_offs<<<SCAN_B, 256, 0, g_hx.s1>>>();
    k_scatter<<<(EE / 4 + 255) / 256, 256, 0, g_hx.s1>>>(ei);
    cudaEventRecord(g_hx.ev_join, g_hx.s1);

    // s0: weight split -> fused embed+abde(l=0)
    k_wsplit<<<NL, 256>>>(Aw, Bw, Dw, Ew);
    k_embed_abde0<<<(NN + 63) / 64, 256>>>(feature, emb_w, emb_b,
                                           Ab, Bb, Db, Eb);

    // join: agg needs CSR
    cudaStreamWaitEvent(0, g_hx.ev_join, 0);
    k_agg<<<(NN + 31) / 32, 256>>>(0);

    for (int l = 1; l < NL; l++) {
        const float* pg = gamma + (l - 1) * HID;
        const float* pb = beta  + (l - 1) * HID;
        k_abde<<<(NN + 63) / 64, 256>>>(
            Ab + l * HID, Bb + l * HID, Db + l * HID, Eb + l * HID,
            pg, pb, l);
        k_agg<<<(NN + 31) / 32, 256>>>(l);
    }
    k_bn_final<<<(NN * HID + 255) / 256, 256>>>(gamma + (NL - 1) * HID,
                                                beta + (NL - 1) * HID, out);
}

// round 15
// speedup vs baseline: 1.0798x; 1.0124x over previous
#include <cuda_runtime.h>
#include <cuda_bf16.h>

#define NN 50000
#define EE 1000000
#define IN_DIM 128
#define HID 64
#define NL 4
#define SCAN_B 196   // ceil(NN/256)

#define GDC_WAIT()   asm volatile("griddepcontrol.wait;" ::: "memory")
#define GDC_LAUNCH() asm volatile("griddepcontrol.launch_dependents;" ::: "memory")

// ---------------- host-side stream/events (created pre-main) ------------------
struct HxStreams {
    cudaStream_t s1;
    cudaEvent_t ev_fork, ev_join;
    HxStreams() {
        cudaStreamCreateWithFlags(&s1, cudaStreamNonBlocking);
        cudaEventCreateWithFlags(&ev_fork, cudaEventDisableTiming);
        cudaEventCreateWithFlags(&ev_join, cudaEventDisableTiming);
    }
};
static HxStreams g_hx;
static cudaLaunchAttribute g_pdl_attr[1];

// ---------------- scratch (static device globals; no allocation) -------------
__device__ float    g_h[NN * HID];     // node features (residual-applied)
__device__ float    g_hp[NN * HID];    // pre-BN layer output
__device__ float    g_A[NN * HID];
__device__ float    g_E[NN * HID];
__device__ unsigned g_BD[NN * 64];     // interleaved: even word = D pack, odd = B pack
__device__ int      g_deg[NN];
__device__ int      g_offs[NN + 1];
__device__ int      g_cursor[NN];
__device__ int      g_csr[EE];
__device__ float    g_stats[NL][2 * HID];
__device__ int      g_bpre[256];
// pre-split weights, swizzled smem layout: [layer][c*32 + (kp ^ ((c&7)<<2))]
__device__ unsigned g_Wh[NL * 256 * 32];
__device__ unsigned g_Wl[NL * 256 * 32];

__device__ __forceinline__ unsigned pack_bf16x2(float a, float b) {
    __nv_bfloat162 h = __floats2bfloat162_rn(a, b);
    return *reinterpret_cast<unsigned*>(&h);
}
__device__ __forceinline__ float2 unpack_bf16x2(unsigned u) {
    __nv_bfloat162 h = *reinterpret_cast<__nv_bfloat162*>(&u);
    return __bfloat1622float2(h);
}
__device__ __forceinline__ float sigmoid_fast(float x) {
    float t;
    asm("tanh.approx.f32 %0, %1;" : "=f"(t) : "f"(0.5f * x));
    return fmaf(t, 0.5f, 0.5f);
}
__device__ __forceinline__ void split_pair(float x0, float x1,
                                           unsigned& hw, unsigned& lw) {
    __nv_bfloat16 h0 = __float2bfloat16(x0);
    __nv_bfloat16 h1 = __float2bfloat16(x1);
    float r0 = x0 - __bfloat162float(h0);
    float r1 = x1 - __bfloat162float(h1);
    __nv_bfloat16 l0 = __float2bfloat16(r0);
    __nv_bfloat16 l1 = __float2bfloat16(r1);
    hw = (unsigned)__bfloat16_as_ushort(h0) | ((unsigned)__bfloat16_as_ushort(h1) << 16);
    lw = (unsigned)__bfloat16_as_ushort(l0) | ((unsigned)__bfloat16_as_ushort(l1) << 16);
}
__device__ __forceinline__ void mma_bf16(float* d, const unsigned* a, const unsigned* b) {
    asm("mma.sync.aligned.m16n8k16.row.col.f32.bf16.bf16.f32 "
        "{%0,%1,%2,%3}, {%4,%5,%6,%7}, {%8,%9}, {%0,%1,%2,%3};"
        : "+f"(d[0]), "+f"(d[1]), "+f"(d[2]), "+f"(d[3])
        : "r"(a[0]), "r"(a[1]), "r"(a[2]), "r"(a[3]), "r"(b[0]), "r"(b[1]));
}

// ---------------- s0 head: weight split + stats clear -------------------------
__global__ void k_wsplit(const float* __restrict__ Aw, const float* __restrict__ Bw,
                         const float* __restrict__ Dw, const float* __restrict__ Ew) {
    int b = blockIdx.x, t = threadIdx.x;
    int i = b * 256 + t;
    if (i < NL * 2 * HID) ((float*)g_stats)[i] = 0.f;
    for (int idx = t; idx < 256 * 32; idx += 256) {
        int c = idx >> 5, kp = idx & 31;
        int sel = c >> 6, cc = c & 63;
        const float* W = (sel == 0) ? Aw : (sel == 1) ? Bw : (sel == 2) ? Dw : Ew;
        float w0 = W[b * HID * HID + (2 * kp) * HID + cc];
        float w1 = W[b * HID * HID + (2 * kp + 1) * HID + cc];
        unsigned hw, lw;
        split_pair(w0, w1, hw, lw);
        int s = b * 8192 + c * 32 + (kp ^ ((c & 7) << 2));
        g_Wh[s] = hw;
        g_Wl[s] = lw;
    }
    GDC_LAUNCH();
}

// ---------------- s1 chain: CSR build -----------------------------------------
__global__ void k_cleardeg() {
    int i = blockIdx.x * blockDim.x + threadIdx.x;
    if (i < NN) g_deg[i] = 0;
}

__global__ void k_hist(const int* __restrict__ ei) {
    int e = (blockIdx.x * blockDim.x + threadIdx.x) * 4;
    if (e < EE) {
        int4 d4 = *(const int4*)&ei[EE + e];
        if (d4.x >= 0 && d4.x < NN) atomicAdd(&g_deg[d4.x], 1);
        if (d4.y >= 0 && d4.y < NN) atomicAdd(&g_deg[d4.y], 1);
        if (d4.z >= 0 && d4.z < NN) atomicAdd(&g_deg[d4.z], 1);
        if (d4.w >= 0 && d4.w < NN) atomicAdd(&g_deg[d4.w], 1);
    }
}

__global__ void k_scan1() {
    __shared__ int sums[224];
    __shared__ int ws[8];
    int t = threadIdx.x, lane = t & 31, w = t >> 5;
    for (int c = t; c < 224; c += 256) sums[c] = 0;
    __syncthreads();
    for (int c = w; c < SCAN_B; c += 8) {
        int s = 0;
        #pragma unroll
        for (int i = 0; i < 8; i++) {
            int idx = c * 256 + i * 32 + lane;
            s += (idx < NN) ? g_deg[idx] : 0;
        }
        #pragma unroll
        for (int o = 16; o; o >>= 1) s += __shfl_down_sync(0xffffffffu, s, o);
        if (lane == 0) sums[c] = s;
    }
    __syncthreads();
    int v = (t < SCAN_B) ? sums[t] : 0;
    int x = v;
    #pragma unroll
    for (int o = 1; o < 32; o <<= 1) {
        int y = __shfl_up_sync(0xffffffffu, x, o);
        if (lane >= o) x += y;
    }
    if (lane == 31) ws[w] = x;
    __syncthreads();
    if (t < 8) {
        int q = ws[t];
        #pragma unroll
        for (int o = 1; o < 8; o <<= 1) {
            int y = __shfl_up_sync(0xffu, q, o);
            if (t >= o) q += y;
        }
        ws[t] = q;
    }
    __syncthreads();
    int incl = x + (w ? ws[w - 1] : 0);
    g_bpre[t] = incl - v;
}

__global__ void k_offs() {
    __shared__ int ws[8];
    int t = threadIdx.x, b = blockIdx.x;
    int i = b * 256 + t;
    int v = (i < NN) ? g_deg[i] : 0;
    int lane = t & 31, wid = t >> 5;
    int x = v;
    #pragma unroll
    for (int o = 1; o < 32; o <<= 1) {
        int y = __shfl_up_sync(0xffffffffu, x, o);
        if (lane >= o) x += y;
    }
    if (lane == 31) ws[wid] = x;
    __syncthreads();
    if (t < 8) {
        int w = ws[t];
        #pragma unroll
        for (int o = 1; o < 8; o <<= 1) {
            int y = __shfl_up_sync(0xffu, w, o);
            if (t >= o) w += y;
        }
        ws[t] = w;
    }
    __syncthreads();
    int incl = x + (wid ? ws[wid - 1] : 0);
    int base = g_bpre[b];
    if (i < NN) {
        g_offs[i + 1] = base + incl;
        g_cursor[i]   = base + incl - v;
    }
    if (i == 0) g_offs[0] = 0;
}

__global__ void k_scatter(const int* __restrict__ ei) {
    int e = (blockIdx.x * blockDim.x + threadIdx.x) * 4;
    if (e < EE) {
        int4 s4 = *(const int4*)&ei[e];
        int4 d4 = *(const int4*)&ei[EE + e];
        if (d4.x >= 0 && d4.x < NN) {
            int pos = atomicAdd(&g_cursor[d4.x], 1);
            if (pos >= 0 && pos < EE) g_csr[pos] = s4.x;
        }
        if (d4.y >= 0 && d4.y < NN) {
            int pos = atomicAdd(&g_cursor[d4.y], 1);
            if (pos >= 0 && pos < EE) g_csr[pos] = s4.y;
        }
        if (d4.z >= 0 && d4.z < NN) {
            int pos = atomicAdd(&g_cursor[d4.z], 1);
            if (pos >= 0 && pos < EE) g_csr[pos] = s4.z;
        }
        if (d4.w >= 0 && d4.w < NN) {
            int pos = atomicAdd(&g_cursor[d4.w], 1);
            if (pos >= 0 && pos < EE) g_csr[pos] = s4.w;
        }
    }
}

// ---------------- fused embed + abde(l=0) -------------------------------------
__global__ __launch_bounds__(256) void k_embed_abde0(
    const float* __restrict__ X, const float* __restrict__ W,
    const float* __restrict__ bias,
    const float* __restrict__ Ab, const float* __restrict__ Bb,
    const float* __restrict__ Db, const float* __restrict__ Eb) {
    __shared__ unsigned Xh[64 * 32], Xl[64 * 32];
    __shared__ unsigned Wh[128 * 32], Wl[128 * 32];
    int t = threadIdx.x;
    int m0 = blockIdx.x * 64;
    int lane = t & 31, w = t >> 5;
    int g = lane >> 2, tig = lane & 3;
    int mt = w & 3, ns = w >> 2;
    int r0 = mt * 16 + g, r1 = r0 + 8;

    // ---- phase 1: embed mainloop (inputs only; pre-wait region) -------------
    float eacc[4][4];
    #pragma unroll
    for (int i = 0; i < 4; i++)
        #pragma unroll
        for (int j = 0; j < 4; j++) eacc[i][j] = 0.f;

    #pragma unroll
    for (int kc = 0; kc < 2; kc++) {
        for (int idx = t; idx < 64 * 16; idx += 256) {
            int r = idx >> 4, c4 = (idx & 15) * 4;
            int m = m0 + r;
            float4 v = make_float4(0.f, 0.f, 0.f, 0.f);
            if (m < NN) v = *(const float4*)&X[m * IN_DIM + kc * 64 + c4];
            int kp0 = c4 >> 1, swz = (r & 7) << 2;
            unsigned hw, lw;
            split_pair(v.x, v.y, hw, lw);
            Xh[r * 32 + (kp0 ^ swz)] = hw;
            Xl[r * 32 + (kp0 ^ swz)] = lw;
            split_pair(v.z, v.w, hw, lw);
            Xh[r * 32 + ((kp0 + 1) ^ swz)] = hw;
            Xl[r * 32 + ((kp0 + 1) ^ swz)] = lw;
        }
        for (int idx = t; idx < 32 * 64; idx += 256) {
            int kp = idx >> 6, c = idx & 63;
            float w0 = W[(kc * 64 + 2 * kp) * HID + c];
            float w1 = W[(kc * 64 + 2 * kp + 1) * HID + c];
            unsigned hw, lw;
            split_pair(w0, w1, hw, lw);
            int s = c * 32 + (kp ^ ((c & 7) << 2));
            Wh[s] = hw;
            Wl[s] = lw;
        }
        __syncthreads();

        int swa = g << 2;
        #pragma unroll
        for (int ks = 0; ks < 4; ks++) {
            int kpa = ks * 8 + tig, kpb = kpa + 4;
            unsigned ah[4], al[4];
            int s0 = r0 * 32 + (kpa ^ swa), s1 = r1 * 32 + (kpa ^ swa);
            int s2 = r0 * 32 + (kpb ^ swa), s3 = r1 * 32 + (kpb ^ swa);
            ah[0] = Xh[s0]; ah[1] = Xh[s1]; ah[2] = Xh[s2]; ah[3] = Xh[s3];
            al[0] = Xl[s0]; al[1] = Xl[s1]; al[2] = Xl[s2]; al[3] = Xl[s3];
            #pragma unroll
            for (int nt = 0; nt < 4; nt++) {
                int c = ns * 32 + nt * 8 + g;
                int swc = (c & 7) << 2;
                int sb0 = c * 32 + (kpa ^ swc);
                int sb1 = c * 32 + (kpb ^ swc);
                unsigned bh[2] = {Wh[sb0], Wh[sb1]};
                unsigned bl[2] = {Wl[sb0], Wl[sb1]};
                mma_bf16(eacc[nt], ah, bh);
                mma_bf16(eacc[nt], al, bh);
                mma_bf16(eacc[nt], ah, bl);
            }
        }
        __syncthreads();
    }

    // ---- phase 2: write h + stage abde X directly from fragments -----------
    int mra = m0 + mt * 16 + g, mrb = mra + 8;
    {
        int swa = g << 2;
        #pragma unroll
        for (int nt = 0; nt < 4; nt++) {
            int cc = ns * 32 + nt * 8 + 2 * tig;
            float b0 = bias[cc], b1 = bias[cc + 1];
            float v0 = eacc[nt][0] + b0, v1 = eacc[nt][1] + b1;
            float v2 = eacc[nt][2] + b0, v3 = eacc[nt][3] + b1;
            if (mra < NN) *(float2*)&g_h[mra * HID + cc] = make_float2(v0, v1);
            else { v0 = 0.f; v1 = 0.f; }
            if (mrb < NN) *(float2*)&g_h[mrb * HID + cc] = make_float2(v2, v3);
            else { v2 = 0.f; v3 = 0.f; }
            int kp = cc >> 1;
            unsigned hw, lw;
            split_pair(v0, v1, hw, lw);
            Xh[r0 * 32 + (kp ^ swa)] = hw;
            Xl[r0 * 32 + (kp ^ swa)] = lw;
            split_pair(v2, v3, hw, lw);
            Xh[r1 * 32 + (kp ^ swa)] = hw;
            Xl[r1 * 32 + (kp ^ swa)] = lw;
        }
    }
    __syncthreads();

    GDC_WAIT();     // wsplit (g_Wh/g_Wl) must be complete before phase 3
    GDC_LAUNCH();

    // ---- phase 3: abde l=0 body --------------------------------------------
    #pragma unroll
    for (int half = 0; half < 2; half++) {
        {
            const uint4* srcH = (const uint4*)(g_Wh + half * 4096);
            const uint4* srcL = (const uint4*)(g_Wl + half * 4096);
            uint4* dstH = (uint4*)Wh;
            uint4* dstL = (uint4*)Wl;
            #pragma unroll
            for (int j = 0; j < 4; j++) {
                dstH[t + j * 256] = srcH[t + j * 256];
                dstL[t + j * 256] = srcL[t + j * 256];
            }
        }
        __syncthreads();

        float acc[8][4];
        #pragma unroll
        for (int i = 0; i < 8; i++)
            #pragma unroll
            for (int j = 0; j < 4; j++) acc[i][j] = 0.f;

        int swa = g << 2;
        #pragma unroll
        for (int ks = 0; ks < 4; ks++) {
            int kpa = ks * 8 + tig, kpb = kpa + 4;
            unsigned ah[4], al[4];
            int s0 = r0 * 32 + (kpa ^ swa), s1 = r1 * 32 + (kpa ^ swa);
            int s2 = r0 * 32 + (kpb ^ swa), s3 = r1 * 32 + (kpb ^ swa);
            ah[0] = Xh[s0]; ah[1] = Xh[s1]; ah[2] = Xh[s2]; ah[3] = Xh[s3];
            al[0] = Xl[s0]; al[1] = Xl[s1]; al[2] = Xl[s2]; al[3] = Xl[s3];
            #pragma unroll
            for (int nt = 0; nt < 8; nt++) {
                int c = ns * 64 + nt * 8 + g;
                int swc = (c & 7) << 2;
                int sb0 = c * 32 + (kpa ^ swc);
                int sb1 = c * 32 + (kpb ^ swc);
                unsigned bh[2] = {Wh[sb0], Wh[sb1]};
                unsigned bl[2] = {Wl[sb0], Wl[sb1]};
                mma_bf16(acc[nt], ah, bh);
                mma_bf16(acc[nt], al, bh);
                mma_bf16(acc[nt], ah, bl);
            }
        }

        int sel = half * 2 + ns;
        const float* bp = (sel == 0) ? Ab : (sel == 1) ? Bb : (sel == 2) ? Db : Eb;
        if (sel == 0 || sel == 3) {
            float* Y = (sel == 0) ? g_A : g_E;
            #pragma unroll
            for (int nt = 0; nt < 8; nt++) {
                int cc = nt * 8 + 2 * tig;
                float b0v = bp[cc], b1v = bp[cc + 1];
                if (mra < NN)
                    *(float2*)&Y[mra * HID + cc] = make_float2(acc[nt][0] + b0v, acc[nt][1] + b1v);
                if (mrb < NN)
                    *(float2*)&Y[mrb * HID + cc] = make_float2(acc[nt][2] + b0v, acc[nt][3] + b1v);
            }
        } else {
            int boff = (sel == 1) ? 1 : 0;
            #pragma unroll
            for (int nt = 0; nt < 8; nt++) {
                int cc = nt * 8 + 2 * tig;
                float b0v = bp[cc], b1v = bp[cc + 1];
                if (mra < NN)
                    g_BD[mra * 64 + cc + boff] = pack_bf16x2(acc[nt][0] + b0v, acc[nt][1] + b1v);
                if (mrb < NN)
                    g_BD[mrb * 64 + cc + boff] = pack_bf16x2(acc[nt][2] + b0v, acc[nt][3] + b1v);
            }
        }
        __syncthreads();
    }
}

// ---------------- layer linears: bf16 MMA, pre-split weights, fused BN -------
// Pre-wait region: W(half0) staging from g_Wh (>=2 steps back in dependency chain).
__global__ __launch_bounds__(256) void k_abde(
    const float* __restrict__ Ab, const float* __restrict__ Bb,
    const float* __restrict__ Db, const float* __restrict__ Eb,
    const float* __restrict__ pg, const float* __restrict__ pb,
    int l) {
    __shared__ unsigned Xh[64 * 32], Xl[64 * 32];
    __shared__ unsigned Wh[128 * 32], Wl[128 * 32];
    int t = threadIdx.x;
    int m0 = blockIdx.x * 64;
    const float invN = 1.f / (float)NN;

    // ---- pre-wait: stage W half0 -------------------------------------------
    {
        const uint4* srcH = (const uint4*)(g_Wh + l * 8192);
        const uint4* srcL = (const uint4*)(g_Wl + l * 8192);
        uint4* dstH = (uint4*)Wh;
        uint4* dstL = (uint4*)Wl;
        #pragma unroll
        for (int j = 0; j < 4; j++) {
            dstH[t + j * 256] = srcH[t + j * 256];
            dstL[t + j * 256] = srcL[t + j * 256];
        }
    }
    GDC_WAIT();     // agg(l-1) outputs (g_hp, g_stats[l-1]) now visible
    GDC_LAUNCH();

    // ---- X staging with fused BN of previous layer --------------------------
    for (int idx = t; idx < 64 * 16; idx += 256) {
        int r = idx >> 4, c4 = (idx & 15) * 4;
        int m = m0 + r;
        float4 v = make_float4(0.f, 0.f, 0.f, 0.f);
        if (m < NN) {
            v = *(const float4*)&g_h[m * HID + c4];
            const float* st = g_stats[l - 1];
            float4 hp = *(const float4*)&g_hp[m * HID + c4];
            #pragma unroll
            for (int j = 0; j < 4; j++) {
                int c = c4 + j;
                float mu  = st[c] * invN;
                float var = st[HID + c] * invN - mu * mu;
                float hpv = (j == 0) ? hp.x : (j == 1) ? hp.y : (j == 2) ? hp.z : hp.w;
                float xn  = (hpv - mu) * rsqrtf(var + 1e-5f);
                float vv  = fmaxf(pg[c] * xn + pb[c], 0.f);
                if (j == 0) v.x += vv; else if (j == 1) v.y += vv;
                else if (j == 2) v.z += vv; else v.w += vv;
            }
            *(float4*)&g_h[m * HID + c4] = v;
        }
        int kp0 = c4 >> 1;
        unsigned hw, lw;
        int swz = (r & 7) << 2;
        split_pair(v.x, v.y, hw, lw);
        Xh[r * 32 + (kp0 ^ swz)] = hw;
        Xl[r * 32 + (kp0 ^ swz)] = lw;
        split_pair(v.z, v.w, hw, lw);
        Xh[r * 32 + ((kp0 + 1) ^ swz)] = hw;
        Xl[r * 32 + ((kp0 + 1) ^ swz)] = lw;
    }
    __syncthreads();

    int lane = t & 31, w = t >> 5;
    int g = lane >> 2, tig = lane & 3;
    int mt = w & 3, ns = w >> 2;
    int r0 = mt * 16 + g, r1 = r0 + 8;
    int mra = m0 + mt * 16 + g, mrb = mra + 8;

    #pragma unroll
    for (int half = 0; half < 2; half++) {
        if (half == 1) {
            __syncthreads();   // all reads of Wh/Wl (half0) done
            const uint4* srcH = (const uint4*)(g_Wh + l * 8192 + 4096);
            const uint4* srcL = (const uint4*)(g_Wl + l * 8192 + 4096);
            uint4* dstH = (uint4*)Wh;
            uint4* dstL = (uint4*)Wl;
            #pragma unroll
            for (int j = 0; j < 4; j++) {
                dstH[t + j * 256] = srcH[t + j * 256];
                dstL[t + j * 256] = srcL[t + j * 256];
            }
            __syncthreads();
        }

        float acc[8][4];
        #pragma unroll
        for (int i = 0; i < 8; i++)
            #pragma unroll
            for (int j = 0; j < 4; j++) acc[i][j] = 0.f;

        int swa0 = (r0 & 7) << 2, swa1 = (r1 & 7) << 2;
        #pragma unroll
        for (int ks = 0; ks < 4; ks++) {
            int kb = ks * 8;
            int kpa = kb + tig, kpb = kb + tig + 4;
            unsigned ah[4], al[4];
            int s0 = r0 * 32 + (kpa ^ swa0), s1 = r1 * 32 + (kpa ^ swa1);
            int s2 = r0 * 32 + (kpb ^ swa0), s3 = r1 * 32 + (kpb ^ swa1);
            ah[0] = Xh[s0]; ah[1] = Xh[s1]; ah[2] = Xh[s2]; ah[3] = Xh[s3];
            al[0] = Xl[s0]; al[1] = Xl[s1]; al[2] = Xl[s2]; al[3] = Xl[s3];
            #pragma unroll
            for (int nt = 0; nt < 8; nt++) {
                int c = ns * 64 + nt * 8 + g;
                int swc = (c & 7) << 2;
                int sb0 = c * 32 + (kpa ^ swc);
                int sb1 = c * 32 + (kpb ^ swc);
                unsigned bh[2] = {Wh[sb0], Wh[sb1]};
                unsigned bl[2] = {Wl[sb0], Wl[sb1]};
                mma_bf16(acc[nt], ah, bh);
                mma_bf16(acc[nt], al, bh);
                mma_bf16(acc[nt], ah, bl);
            }
        }

        int sel = half * 2 + ns;
        const float* bp = (sel == 0) ? Ab : (sel == 1) ? Bb : (sel == 2) ? Db : Eb;
        if (sel == 0 || sel == 3) {
            float* Y = (sel == 0) ? g_A : g_E;
            #pragma unroll
            for (int nt = 0; nt < 8; nt++) {
                int cc = nt * 8 + 2 * tig;
                float b0v = bp[cc], b1v = bp[cc + 1];
                if (mra < NN)
                    *(float2*)&Y[mra * HID + cc] = make_float2(acc[nt][0] + b0v, acc[nt][1] + b1v);
                if (mrb < NN)
                    *(float2*)&Y[mrb * HID + cc] = make_float2(acc[nt][2] + b0v, acc[nt][3] + b1v);
            }
        } else {
            int boff = (sel == 1) ? 1 : 0;
            #pragma unroll
            for (int nt = 0; nt < 8; nt++) {
                int cc = nt * 8 + 2 * tig;
                float b0v = bp[cc], b1v = bp[cc + 1];
                if (mra < NN)
                    g_BD[mra * 64 + cc + boff] = pack_bf16x2(acc[nt][0] + b0v, acc[nt][1] + b1v);
                if (mrb < NN)
                    g_BD[mrb * 64 + cc + boff] = pack_bf16x2(acc[nt][2] + b0v, acc[nt][3] + b1v);
            }
        }
    }
}

// ---------------- edge aggregation + fused BN stats (8-edge unrolled) ---------
__global__ __launch_bounds__(256) void k_agg(int l) {
    __shared__ float red_s[8][64], red_q[8][64];
    GDC_WAIT();     // abde(l) outputs visible
    GDC_LAUNCH();
    int w = threadIdx.x >> 5, lane = threadIdx.x & 31;
    int base = (blockIdx.x * 8 + w) * 4;
    float sx = 0.f, sy = 0.f, qx = 0.f, qy = 0.f;
    #pragma unroll 1
    for (int i = 0; i < 4; i++) {
        int gw = base + i;
        if (gw >= NN) break;
        int s0 = g_offs[gw], s1 = g_offs[gw + 1];
        int off = gw * HID + lane * 2;
        float2 el = *(const float2*)&g_E[off];
        float nx = 0.f, ny = 0.f, dx = 0.f, dy = 0.f;
        int k = s0;
        for (; k + 7 < s1; k += 8) {
            int sidx[8];
            uint2 v[8];
            #pragma unroll
            for (int j = 0; j < 8; j++) sidx[j] = g_csr[k + j];
            #pragma unroll
            for (int j = 0; j < 8; j++) v[j] = *(const uint2*)&g_BD[sidx[j] * 64 + lane * 2];
            #pragma unroll
            for (int j = 0; j < 8; j++) {
                float2 d = unpack_bf16x2(v[j].x), b = unpack_bf16x2(v[j].y);
                float gx = sigmoid_fast(d.x + el.x);
                float gy = sigmoid_fast(d.y + el.y);
                nx += gx * b.x; ny += gy * b.y;
                dx += gx;       dy += gy;
            }
        }
        for (; k + 3 < s1; k += 4) {
            int sidx[4];
            uint2 v[4];
            #pragma unroll
            for (int j = 0; j < 4; j++) sidx[j] = g_csr[k + j];
            #pragma unroll
            for (int j = 0; j < 4; j++) v[j] = *(const uint2*)&g_BD[sidx[j] * 64 + lane * 2];
            #pragma unroll
            for (int j = 0; j < 4; j++) {
                float2 d = unpack_bf16x2(v[j].x), b = unpack_bf16x2(v[j].y);
                float gx = sigmoid_fast(d.x + el.x);
                float gy = sigmoid_fast(d.y + el.y);
                nx += gx * b.x; ny += gy * b.y;
                dx += gx;       dy += gy;
            }
        }
        for (; k < s1; k++) {
            int sa = g_csr[k];
            uint2 va = *(const uint2*)&g_BD[sa * 64 + lane * 2];
            float2 d = unpack_bf16x2(va.x), b = unpack_bf16x2(va.y);
            float gx = sigmoid_fast(d.x + el.x);
            float gy = sigmoid_fast(d.y + el.y);
            nx += gx * b.x; ny += gy * b.y;
            dx += gx;       dy += gy;
        }
        float2 aa = *(const float2*)&g_A[off];
        float ox = aa.x + nx / (dx + 1e-6f);
        float oy = aa.y + ny / (dy + 1e-6f);
        *(float2*)&g_hp[off] = make_float2(ox, oy);
        sx += ox; sy += oy; qx += ox * ox; qy += oy * oy;
    }
    red_s[w][lane * 2] = sx;  red_s[w][lane * 2 + 1] = sy;
    red_q[w][lane * 2] = qx;  red_q[w][lane * 2 + 1] = qy;
    __syncthreads();
    int t = threadIdx.x;
    if (t < 64) {
        float s = 0.f, q = 0.f;
        #pragma unroll
        for (int ww = 0; ww < 8; ww++) { s += red_s[ww][t]; q += red_q[ww][t]; }
        atomicAdd(&g_stats[l][t], s);
        atomicAdd(&g_stats[l][HID + t], q);
    }
}

// ---------------- final BN/ReLU/residual -> d_out -----------------------------
__global__ __launch_bounds__(256) void k_bn_final(const float* __restrict__ gamma,
                                                  const float* __restrict__ beta,
                                                  float* __restrict__ out) {
    GDC_WAIT();
    int idx = blockIdx.x * blockDim.x + threadIdx.x;
    if (idx >= NN * HID) return;
    int c = idx & 63;
    const float* st = g_stats[NL - 1];
    const float invN = 1.f / (float)NN;
    float mu  = st[c] * invN;
    float var = st[HID + c] * invN - mu * mu;
    float xn = (g_hp[idx] - mu) * rsqrtf(var + 1e-5f);
    float v = fmaxf(gamma[c] * xn + beta[c], 0.f);
    out[idx] = g_h[idx] + v;
}

// ---------------- launch ------------------------------------------------------
extern "C" void kernel_launch(void* const* d_in, const int* in_sizes, int n_in,
                              void* d_out, int out_size) {
    const float* feature = (const float*)d_in[0];
    const int*   ei      = (const int*)d_in[1];     // int32 (JAX x64 disabled)
    const float* emb_w   = (const float*)d_in[2];
    const float* emb_b   = (const float*)d_in[3];
    const float* Aw      = (const float*)d_in[4];
    const float* Ab      = (const float*)d_in[5];
    const float* Bw      = (const float*)d_in[6];
    const float* Bb      = (const float*)d_in[7];
    const float* Dw      = (const float*)d_in[8];
    const float* Db      = (const float*)d_in[9];
    const float* Ew      = (const float*)d_in[10];
    const float* Eb      = (const float*)d_in[11];
    const float* gamma   = (const float*)d_in[12];
    const float* beta    = (const float*)d_in[13];
    float* out = (float*)d_out;

    g_pdl_attr[0].id = cudaLaunchAttributeProgrammaticStreamSerialization;
    g_pdl_attr[0].val.programmaticStreamSerializationAllowed = 1;

    // fork: CSR build on side stream, GEMM chain on origin stream
    cudaEventRecord(g_hx.ev_fork, 0);
    cudaStreamWaitEvent(g_hx.s1, g_hx.ev_fork, 0);

    // s1: CSR build (plain launches)
    k_cleardeg<<<(NN + 255) / 256, 256, 0, g_hx.s1>>>();
    k_hist<<<(EE / 4 + 255) / 256, 256, 0, g_hx.s1>>>(ei);
    k_scan1<<<1, 256, 0, g_hx.s1>>>();
    k_offs<<<SCAN_B, 256, 0, g_hx.s1>>>();
    k_scatter<<<(EE / 4 + 255) / 256, 256, 0, g_hx.s1>>>(ei);
    cudaEventRecord(g_hx.ev_join, g_hx.s1);

    // s0: weight split (plain) -> PDL chain
    k_wsplit<<<NL, 256>>>(Aw, Bw, Dw, Ew);

    {
        cudaLaunchConfig_t cfg = {};
        cfg.gridDim = dim3((NN + 63) / 64);
        cfg.blockDim = dim3(256);
        cfg.stream = 0;
        cfg.attrs = g_pdl_attr;
        cfg.numAttrs = 1;
        cudaLaunchKernelEx(&cfg, k_embed_abde0, feature, emb_w, emb_b,
                           Ab, Bb, Db, Eb);
    }

    // join: agg needs CSR
    cudaStreamWaitEvent(0, g_hx.ev_join, 0);
    {
        cudaLaunchConfig_t cfg = {};
        cfg.gridDim = dim3((NN + 31) / 32);
        cfg.blockDim = dim3(256);
        cfg.stream = 0;
        cfg.attrs = g_pdl_attr;
        cfg.numAttrs = 1;
        cudaLaunchKernelEx(&cfg, k_agg, 0);
    }

    for (int l = 1; l < NL; l++) {
        const float* pg = gamma + (l - 1) * HID;
        const float* pb = beta  + (l - 1) * HID;
        {
            cudaLaunchConfig_t cfg = {};
            cfg.gridDim = dim3((NN + 63) / 64);
            cfg.blockDim = dim3(256);
            cfg.stream = 0;
            cfg.attrs = g_pdl_attr;
            cfg.numAttrs = 1;
            cudaLaunchKernelEx(&cfg, k_abde,
                               (const float*)(Ab + l * HID), (const float*)(Bb + l * HID),
                               (const float*)(Db + l * HID), (const float*)(Eb + l * HID),
                               pg, pb, l);
        }
        {
            cudaLaunchConfig_t cfg = {};
            cfg.gridDim = dim3((NN + 31) / 32);
            cfg.blockDim = dim3(256);
            cfg.stream = 0;
            cfg.attrs = g_pdl_attr;
            cfg.numAttrs = 1;
            cudaLaunchKernelEx(&cfg, k_agg, l);
        }
    }
    {
        cudaLaunchConfig_t cfg = {};
        cfg.gridDim = dim3((NN * HID + 255) / 256);
        cfg.blockDim = dim3(256);
        cfg.stream = 0;
        cfg.attrs = g_pdl_attr;
        cfg.numAttrs = 1;
        cudaLaunchKernelEx(&cfg, k_bn_final,
                           (const float*)(gamma + (NL - 1) * HID),
                           (const float*)(beta + (NL - 1) * HID), out);
    }
}

// round 16
// speedup vs baseline: 1.0844x; 1.0042x over previous
#include <cuda_runtime.h>
#include <cuda_bf16.h>

#define NN 50000
#define EE 1000000
#define IN_DIM 128
#define HID 64
#define NL 4
#define SCAN_B 196   // ceil(NN/256)

#define GDC_WAIT()   asm volatile("griddepcontrol.wait;" ::: "memory")
#define GDC_LAUNCH() asm volatile("griddepcontrol.launch_dependents;" ::: "memory")

// ---------------- host-side stream/events (created pre-main) ------------------
struct HxStreams {
    cudaStream_t s1;
    cudaEvent_t ev_fork, ev_join;
    HxStreams() {
        cudaStreamCreateWithFlags(&s1, cudaStreamNonBlocking);
        cudaEventCreateWithFlags(&ev_fork, cudaEventDisableTiming);
        cudaEventCreateWithFlags(&ev_join, cudaEventDisableTiming);
    }
};
static HxStreams g_hx;
static cudaLaunchAttribute g_pdl_attr[1];

// ---------------- scratch (static device globals; no allocation) -------------
__device__ float    g_h[NN * HID];     // node features (residual-applied)
__device__ float    g_hp[NN * HID];    // pre-BN layer output
__device__ float    g_A[NN * HID];
__device__ float    g_E[NN * HID];
__device__ unsigned g_BD[NN * 64];     // interleaved: even word = D pack, odd = B pack
__device__ int      g_deg[NN];         // zero between launches (cleared in k_offs)
__device__ int      g_offs[NN + 1];
__device__ int      g_cursor[NN];
__device__ int      g_csr[EE];
__device__ float    g_stats[NL][2 * HID];
__device__ int      g_bpre[256];
// pre-split weights, swizzled smem layout: [layer][c*32 + (kp ^ ((c&7)<<2))]
__device__ unsigned g_Wh[NL * 256 * 32];
__device__ unsigned g_Wl[NL * 256 * 32];

__device__ __forceinline__ unsigned pack_bf16x2(float a, float b) {
    __nv_bfloat162 h = __floats2bfloat162_rn(a, b);
    return *reinterpret_cast<unsigned*>(&h);
}
__device__ __forceinline__ float2 unpack_bf16x2(unsigned u) {
    __nv_bfloat162 h = *reinterpret_cast<__nv_bfloat162*>(&u);
    return __bfloat1622float2(h);
}
__device__ __forceinline__ float sigmoid_fast(float x) {
    float t;
    asm("tanh.approx.f32 %0, %1;" : "=f"(t) : "f"(0.5f * x));
    return fmaf(t, 0.5f, 0.5f);
}
__device__ __forceinline__ void split_pair(float x0, float x1,
                                           unsigned& hw, unsigned& lw) {
    __nv_bfloat16 h0 = __float2bfloat16(x0);
    __nv_bfloat16 h1 = __float2bfloat16(x1);
    float r0 = x0 - __bfloat162float(h0);
    float r1 = x1 - __bfloat162float(h1);
    __nv_bfloat16 l0 = __float2bfloat16(r0);
    __nv_bfloat16 l1 = __float2bfloat16(r1);
    hw = (unsigned)__bfloat16_as_ushort(h0) | ((unsigned)__bfloat16_as_ushort(h1) << 16);
    lw = (unsigned)__bfloat16_as_ushort(l0) | ((unsigned)__bfloat16_as_ushort(l1) << 16);
}
__device__ __forceinline__ void mma_bf16(float* d, const unsigned* a, const unsigned* b) {
    asm("mma.sync.aligned.m16n8k16.row.col.f32.bf16.bf16.f32 "
        "{%0,%1,%2,%3}, {%4,%5,%6,%7}, {%8,%9}, {%0,%1,%2,%3};"
        : "+f"(d[0]), "+f"(d[1]), "+f"(d[2]), "+f"(d[3])
        : "r"(a[0]), "r"(a[1]), "r"(a[2]), "r"(a[3]), "r"(b[0]), "r"(b[1]));
}

// ---------------- s0 head: weight split + stats clear -------------------------
__global__ void k_wsplit(const float* __restrict__ Aw, const float* __restrict__ Bw,
                         const float* __restrict__ Dw, const float* __restrict__ Ew) {
    int b = blockIdx.x, t = threadIdx.x;
    int i = b * 256 + t;
    if (i < NL * 2 * HID) ((float*)g_stats)[i] = 0.f;
    for (int idx = t; idx < 256 * 32; idx += 256) {
        int c = idx >> 5, kp = idx & 31;
        int sel = c >> 6, cc = c & 63;
        const float* W = (sel == 0) ? Aw : (sel == 1) ? Bw : (sel == 2) ? Dw : Ew;
        float w0 = W[b * HID * HID + (2 * kp) * HID + cc];
        float w1 = W[b * HID * HID + (2 * kp + 1) * HID + cc];
        unsigned hw, lw;
        split_pair(w0, w1, hw, lw);
        int s = b * 8192 + c * 32 + (kp ^ ((c & 7) << 2));
        g_Wh[s] = hw;
        g_Wl[s] = lw;
    }
    GDC_LAUNCH();
}

// ---------------- s1 chain: CSR build (deg pre-zeroed) ------------------------
__global__ void k_hist(const int* __restrict__ ei) {
    int e = (blockIdx.x * blockDim.x + threadIdx.x) * 4;
    if (e < EE) {
        int4 d4 = *(const int4*)&ei[EE + e];
        if (d4.x >= 0 && d4.x < NN) atomicAdd(&g_deg[d4.x], 1);
        if (d4.y >= 0 && d4.y < NN) atomicAdd(&g_deg[d4.y], 1);
        if (d4.z >= 0 && d4.z < NN) atomicAdd(&g_deg[d4.z], 1);
        if (d4.w >= 0 && d4.w < NN) atomicAdd(&g_deg[d4.w], 1);
    }
    GDC_LAUNCH();
}

__global__ void k_scan1() {
    __shared__ int sums[224];
    __shared__ int ws[8];
    GDC_WAIT();
    int t = threadIdx.x, lane = t & 31, w = t >> 5;
    for (int c = t; c < 224; c += 256) sums[c] = 0;
    __syncthreads();
    for (int c = w; c < SCAN_B; c += 8) {
        int s = 0;
        #pragma unroll
        for (int i = 0; i < 8; i++) {
            int idx = c * 256 + i * 32 + lane;
            s += (idx < NN) ? g_deg[idx] : 0;
        }
        #pragma unroll
        for (int o = 16; o; o >>= 1) s += __shfl_down_sync(0xffffffffu, s, o);
        if (lane == 0) sums[c] = s;
    }
    __syncthreads();
    int v = (t < SCAN_B) ? sums[t] : 0;
    int x = v;
    #pragma unroll
    for (int o = 1; o < 32; o <<= 1) {
        int y = __shfl_up_sync(0xffffffffu, x, o);
        if (lane >= o) x += y;
    }
    if (lane == 31) ws[w] = x;
    __syncthreads();
    if (t < 8) {
        int q = ws[t];
        #pragma unroll
        for (int o = 1; o < 8; o <<= 1) {
            int y = __shfl_up_sync(0xffu, q, o);
            if (t >= o) q += y;
        }
        ws[t] = q;
    }
    __syncthreads();
    int incl = x + (w ? ws[w - 1] : 0);
    g_bpre[t] = incl - v;
    GDC_LAUNCH();
}

__global__ void k_offs() {
    __shared__ int ws[8];
    GDC_WAIT();
    int t = threadIdx.x, b = blockIdx.x;
    int i = b * 256 + t;
    int v = (i < NN) ? g_deg[i] : 0;
    int lane = t & 31, wid = t >> 5;
    int x = v;
    #pragma unroll
    for (int o = 1; o < 32; o <<= 1) {
        int y = __shfl_up_sync(0xffffffffu, x, o);
        if (lane >= o) x += y;
    }
    if (lane == 31) ws[wid] = x;
    __syncthreads();
    if (t < 8) {
        int w = ws[t];
        #pragma unroll
        for (int o = 1; o < 8; o <<= 1) {
            int y = __shfl_up_sync(0xffu, w, o);
            if (t >= o) w += y;
        }
        ws[t] = w;
    }
    __syncthreads();
    int incl = x + (wid ? ws[wid - 1] : 0);
    int base = g_bpre[b];
    if (i < NN) {
        g_offs[i + 1] = base + incl;
        g_cursor[i]   = base + incl - v;
        g_deg[i]      = 0;            // leave clean for next launch
    }
    if (i == 0) g_offs[0] = 0;
    GDC_LAUNCH();
}

__global__ void k_scatter(const int* __restrict__ ei) {
    GDC_WAIT();
    int e = (blockIdx.x * blockDim.x + threadIdx.x) * 4;
    if (e < EE) {
        int4 s4 = *(const int4*)&ei[e];
        int4 d4 = *(const int4*)&ei[EE + e];
        if (d4.x >= 0 && d4.x < NN) {
            int pos = atomicAdd(&g_cursor[d4.x], 1);
            if (pos >= 0 && pos < EE) g_csr[pos] = s4.x;
        }
        if (d4.y >= 0 && d4.y < NN) {
            int pos = atomicAdd(&g_cursor[d4.y], 1);
            if (pos >= 0 && pos < EE) g_csr[pos] = s4.y;
        }
        if (d4.z >= 0 && d4.z < NN) {
            int pos = atomicAdd(&g_cursor[d4.z], 1);
            if (pos >= 0 && pos < EE) g_csr[pos] = s4.z;
        }
        if (d4.w >= 0 && d4.w < NN) {
            int pos = atomicAdd(&g_cursor[d4.w], 1);
            if (pos >= 0 && pos < EE) g_csr[pos] = s4.w;
        }
    }
}

// ---------------- fused embed + abde(l=0) -------------------------------------
__global__ __launch_bounds__(256) void k_embed_abde0(
    const float* __restrict__ X, const float* __restrict__ W,
    const float* __restrict__ bias,
    const float* __restrict__ Ab, const float* __restrict__ Bb,
    const float* __restrict__ Db, const float* __restrict__ Eb) {
    __shared__ unsigned Xh[64 * 32], Xl[64 * 32];
    __shared__ unsigned Wh[128 * 32], Wl[128 * 32];
    int t = threadIdx.x;
    int m0 = blockIdx.x * 64;
    int lane = t & 31, w = t >> 5;
    int g = lane >> 2, tig = lane & 3;
    int mt = w & 3, ns = w >> 2;
    int r0 = mt * 16 + g, r1 = r0 + 8;

    // ---- phase 1: embed mainloop (inputs only; pre-wait region) -------------
    float eacc[4][4];
    #pragma unroll
    for (int i = 0; i < 4; i++)
        #pragma unroll
        for (int j = 0; j < 4; j++) eacc[i][j] = 0.f;

    #pragma unroll
    for (int kc = 0; kc < 2; kc++) {
        for (int idx = t; idx < 64 * 16; idx += 256) {
            int r = idx >> 4, c4 = (idx & 15) * 4;
            int m = m0 + r;
            float4 v = make_float4(0.f, 0.f, 0.f, 0.f);
            if (m < NN) v = *(const float4*)&X[m * IN_DIM + kc * 64 + c4];
            int kp0 = c4 >> 1, swz = (r & 7) << 2;
            unsigned hw, lw;
            split_pair(v.x, v.y, hw, lw);
            Xh[r * 32 + (kp0 ^ swz)] = hw;
            Xl[r * 32 + (kp0 ^ swz)] = lw;
            split_pair(v.z, v.w, hw, lw);
            Xh[r * 32 + ((kp0 + 1) ^ swz)] = hw;
            Xl[r * 32 + ((kp0 + 1) ^ swz)] = lw;
        }
        for (int idx = t; idx < 32 * 64; idx += 256) {
            int kp = idx >> 6, c = idx & 63;
            float w0 = W[(kc * 64 + 2 * kp) * HID + c];
            float w1 = W[(kc * 64 + 2 * kp + 1) * HID + c];
            unsigned hw, lw;
            split_pair(w0, w1, hw, lw);
            int s = c * 32 + (kp ^ ((c & 7) << 2));
            Wh[s] = hw;
            Wl[s] = lw;
        }
        __syncthreads();

        int swa = g << 2;
        #pragma unroll
        for (int ks = 0; ks < 4; ks++) {
            int kpa = ks * 8 + tig, kpb = kpa + 4;
            unsigned ah[4], al[4];
            int s0 = r0 * 32 + (kpa ^ swa), s1 = r1 * 32 + (kpa ^ swa);
            int s2 = r0 * 32 + (kpb ^ swa), s3 = r1 * 32 + (kpb ^ swa);
            ah[0] = Xh[s0]; ah[1] = Xh[s1]; ah[2] = Xh[s2]; ah[3] = Xh[s3];
            al[0] = Xl[s0]; al[1] = Xl[s1]; al[2] = Xl[s2]; al[3] = Xl[s3];
            #pragma unroll
            for (int nt = 0; nt < 4; nt++) {
                int c = ns * 32 + nt * 8 + g;
                int swc = (c & 7) << 2;
                int sb0 = c * 32 + (kpa ^ swc);
                int sb1 = c * 32 + (kpb ^ swc);
                unsigned bh[2] = {Wh[sb0], Wh[sb1]};
                unsigned bl[2] = {Wl[sb0], Wl[sb1]};
                mma_bf16(eacc[nt], ah, bh);
                mma_bf16(eacc[nt], al, bh);
                mma_bf16(eacc[nt], ah, bl);
            }
        }
        __syncthreads();
    }

    // ---- phase 2: write h + stage abde X directly from fragments -----------
    int mra = m0 + mt * 16 + g, mrb = mra + 8;
    {
        int swa = g << 2;
        #pragma unroll
        for (int nt = 0; nt < 4; nt++) {
            int cc = ns * 32 + nt * 8 + 2 * tig;
            float b0 = bias[cc], b1 = bias[cc + 1];
            float v0 = eacc[nt][0] + b0, v1 = eacc[nt][1] + b1;
            float v2 = eacc[nt][2] + b0, v3 = eacc[nt][3] + b1;
            if (mra < NN) *(float2*)&g_h[mra * HID + cc] = make_float2(v0, v1);
            else { v0 = 0.f; v1 = 0.f; }
            if (mrb < NN) *(float2*)&g_h[mrb * HID + cc] = make_float2(v2, v3);
            else { v2 = 0.f; v3 = 0.f; }
            int kp = cc >> 1;
            unsigned hw, lw;
            split_pair(v0, v1, hw, lw);
            Xh[r0 * 32 + (kp ^ swa)] = hw;
            Xl[r0 * 32 + (kp ^ swa)] = lw;
            split_pair(v2, v3, hw, lw);
            Xh[r1 * 32 + (kp ^ swa)] = hw;
            Xl[r1 * 32 + (kp ^ swa)] = lw;
        }
    }
    __syncthreads();

    GDC_WAIT();     // wsplit (g_Wh/g_Wl) must be complete before phase 3
    GDC_LAUNCH();

    // ---- phase 3: abde l=0 body --------------------------------------------
    #pragma unroll
    for (int half = 0; half < 2; half++) {
        {
            const uint4* srcH = (const uint4*)(g_Wh + half * 4096);
            const uint4* srcL = (const uint4*)(g_Wl + half * 4096);
            uint4* dstH = (uint4*)Wh;
            uint4* dstL = (uint4*)Wl;
            #pragma unroll
            for (int j = 0; j < 4; j++) {
                dstH[t + j * 256] = srcH[t + j * 256];
                dstL[t + j * 256] = srcL[t + j * 256];
            }
        }
        __syncthreads();

        float acc[8][4];
        #pragma unroll
        for (int i = 0; i < 8; i++)
            #pragma unroll
            for (int j = 0; j < 4; j++) acc[i][j] = 0.f;

        int swa = g << 2;
        #pragma unroll
        for (int ks = 0; ks < 4; ks++) {
            int kpa = ks * 8 + tig, kpb = kpa + 4;
            unsigned ah[4], al[4];
            int s0 = r0 * 32 + (kpa ^ swa), s1 = r1 * 32 + (kpa ^ swa);
            int s2 = r0 * 32 + (kpb ^ swa), s3 = r1 * 32 + (kpb ^ swa);
            ah[0] = Xh[s0]; ah[1] = Xh[s1]; ah[2] = Xh[s2]; ah[3] = Xh[s3];
            al[0] = Xl[s0]; al[1] = Xl[s1]; al[2] = Xl[s2]; al[3] = Xl[s3];
            #pragma unroll
            for (int nt = 0; nt < 8; nt++) {
                int c = ns * 64 + nt * 8 + g;
                int swc = (c & 7) << 2;
                int sb0 = c * 32 + (kpa ^ swc);
                int sb1 = c * 32 + (kpb ^ swc);
                unsigned bh[2] = {Wh[sb0], Wh[sb1]};
                unsigned bl[2] = {Wl[sb0], Wl[sb1]};
                mma_bf16(acc[nt], ah, bh);
                mma_bf16(acc[nt], al, bh);
                mma_bf16(acc[nt], ah, bl);
            }
        }

        int sel = half * 2 + ns;
        const float* bp = (sel == 0) ? Ab : (sel == 1) ? Bb : (sel == 2) ? Db : Eb;
        if (sel == 0 || sel == 3) {
            float* Y = (sel == 0) ? g_A : g_E;
            #pragma unroll
            for (int nt = 0; nt < 8; nt++) {
                int cc = nt * 8 + 2 * tig;
                float b0v = bp[cc], b1v = bp[cc + 1];
                if (mra < NN)
                    *(float2*)&Y[mra * HID + cc] = make_float2(acc[nt][0] + b0v, acc[nt][1] + b1v);
                if (mrb < NN)
                    *(float2*)&Y[mrb * HID + cc] = make_float2(acc[nt][2] + b0v, acc[nt][3] + b1v);
            }
        } else {
            int boff = (sel == 1) ? 1 : 0;
            #pragma unroll
            for (int nt = 0; nt < 8; nt++) {
                int cc = nt * 8 + 2 * tig;
                float b0v = bp[cc], b1v = bp[cc + 1];
                if (mra < NN)
                    g_BD[mra * 64 + cc + boff] = pack_bf16x2(acc[nt][0] + b0v, acc[nt][1] + b1v);
                if (mrb < NN)
                    g_BD[mrb * 64 + cc + boff] = pack_bf16x2(acc[nt][2] + b0v, acc[nt][3] + b1v);
            }
        }
        __syncthreads();
    }
}

// ---------------- layer linears: bf16 MMA, 2mt x 4nt warp mapping ------------
__global__ __launch_bounds__(256) void k_abde(
    const float* __restrict__ Ab, const float* __restrict__ Bb,
    const float* __restrict__ Db, const float* __restrict__ Eb,
    const float* __restrict__ pg, const float* __restrict__ pb,
    int l) {
    __shared__ unsigned Xh[64 * 32], Xl[64 * 32];
    __shared__ unsigned Wh[128 * 32], Wl[128 * 32];
    int t = threadIdx.x;
    int m0 = blockIdx.x * 64;
    const float invN = 1.f / (float)NN;

    // ---- pre-wait: stage W half0 -------------------------------------------
    {
        const uint4* srcH = (const uint4*)(g_Wh + l * 8192);
        const uint4* srcL = (const uint4*)(g_Wl + l * 8192);
        uint4* dstH = (uint4*)Wh;
        uint4* dstL = (uint4*)Wl;
        #pragma unroll
        for (int j = 0; j < 4; j++) {
            dstH[t + j * 256] = srcH[t + j * 256];
            dstL[t + j * 256] = srcL[t + j * 256];
        }
    }
    GDC_WAIT();
    GDC_LAUNCH();

    // ---- X staging with fused BN of previous layer --------------------------
    for (int idx = t; idx < 64 * 16; idx += 256) {
        int r = idx >> 4, c4 = (idx & 15) * 4;
        int m = m0 + r;
        float4 v = make_float4(0.f, 0.f, 0.f, 0.f);
        if (m < NN) {
            v = *(const float4*)&g_h[m * HID + c4];
            const float* st = g_stats[l - 1];
            float4 hp = *(const float4*)&g_hp[m * HID + c4];
            #pragma unroll
            for (int j = 0; j < 4; j++) {
                int c = c4 + j;
                float mu  = st[c] * invN;
                float var = st[HID + c] * invN - mu * mu;
                float hpv = (j == 0) ? hp.x : (j == 1) ? hp.y : (j == 2) ? hp.z : hp.w;
                float xn  = (hpv - mu) * rsqrtf(var + 1e-5f);
                float vv  = fmaxf(pg[c] * xn + pb[c], 0.f);
                if (j == 0) v.x += vv; else if (j == 1) v.y += vv;
                else if (j == 2) v.z += vv; else v.w += vv;
            }
            *(float4*)&g_h[m * HID + c4] = v;
        }
        int kp0 = c4 >> 1;
        unsigned hw, lw;
        int swz = (r & 7) << 2;
        split_pair(v.x, v.y, hw, lw);
        Xh[r * 32 + (kp0 ^ swz)] = hw;
        Xl[r * 32 + (kp0 ^ swz)] = lw;
        split_pair(v.z, v.w, hw, lw);
        Xh[r * 32 + ((kp0 + 1) ^ swz)] = hw;
        Xl[r * 32 + ((kp0 + 1) ^ swz)] = lw;
    }
    __syncthreads();

    int lane = t & 31, w = t >> 5;
    int g = lane >> 2, tig = lane & 3;
    int mt0 = (w & 1) * 2;          // m-tiles mt0, mt0+1
    int nq = w >> 1;                // 0..3: n-tile group (4 n-tiles) within half
    int rA0 = mt0 * 16 + g, rA1 = rA0 + 8;
    int rB0 = (mt0 + 1) * 16 + g, rB1 = rB0 + 8;
    int swa = g << 2;               // same for all four rows ((r&7)==g)

    #pragma unroll
    for (int half = 0; half < 2; half++) {
        if (half == 1) {
            __syncthreads();
            const uint4* srcH = (const uint4*)(g_Wh + l * 8192 + 4096);
            const uint4* srcL = (const uint4*)(g_Wl + l * 8192 + 4096);
            uint4* dstH = (uint4*)Wh;
            uint4* dstL = (uint4*)Wl;
            #pragma unroll
            for (int j = 0; j < 4; j++) {
                dstH[t + j * 256] = srcH[t + j * 256];
                dstL[t + j * 256] = srcL[t + j * 256];
            }
            __syncthreads();
        }

        float acc[2][4][4];
        #pragma unroll
        for (int mi = 0; mi < 2; mi++)
            #pragma unroll
            for (int j = 0; j < 4; j++)
                #pragma unroll
                for (int q = 0; q < 4; q++) acc[mi][j][q] = 0.f;

        #pragma unroll
        for (int ks = 0; ks < 4; ks++) {
            int kpa = ks * 8 + tig, kpb = kpa + 4;
            int oa = kpa ^ swa, ob = kpb ^ swa;
            unsigned a0h[4], a0l[4], a1h[4], a1l[4];
            a0h[0] = Xh[rA0 * 32 + oa]; a0h[1] = Xh[rA1 * 32 + oa];
            a0h[2] = Xh[rA0 * 32 + ob]; a0h[3] = Xh[rA1 * 32 + ob];
            a0l[0] = Xl[rA0 * 32 + oa]; a0l[1] = Xl[rA1 * 32 + oa];
            a0l[2] = Xl[rA0 * 32 + ob]; a0l[3] = Xl[rA1 * 32 + ob];
            a1h[0] = Xh[rB0 * 32 + oa]; a1h[1] = Xh[rB1 * 32 + oa];
            a1h[2] = Xh[rB0 * 32 + ob]; a1h[3] = Xh[rB1 * 32 + ob];
            a1l[0] = Xl[rB0 * 32 + oa]; a1l[1] = Xl[rB1 * 32 + oa];
            a1l[2] = Xl[rB0 * 32 + ob]; a1l[3] = Xl[rB1 * 32 + ob];
            #pragma unroll
            for (int j = 0; j < 4; j++) {
                int c = (nq * 4 + j) * 8 + g;       // 0..127 within half
                int swc = (c & 7) << 2;
                int sb0 = c * 32 + (kpa ^ swc);
                int sb1 = c * 32 + (kpb ^ swc);
                unsigned bh[2] = {Wh[sb0], Wh[sb1]};
                unsigned bl[2] = {Wl[sb0], Wl[sb1]};
                mma_bf16(acc[0][j], a0h, bh);
                mma_bf16(acc[0][j], a0l, bh);
                mma_bf16(acc[0][j], a0h, bl);
                mma_bf16(acc[1][j], a1h, bh);
                mma_bf16(acc[1][j], a1l, bh);
                mma_bf16(acc[1][j], a1h, bl);
            }
        }

        int sel = half * 2 + (nq >> 1);
        const float* bp = (sel == 0) ? Ab : (sel == 1) ? Bb : (sel == 2) ? Db : Eb;
        #pragma unroll
        for (int mi = 0; mi < 2; mi++) {
            int mra = m0 + (mt0 + mi) * 16 + g, mrb = mra + 8;
            if (sel == 0 || sel == 3) {
                float* Y = (sel == 0) ? g_A : g_E;
                #pragma unroll
                for (int j = 0; j < 4; j++) {
                    int cc = (((nq * 4 + j) * 8) & 63) + 2 * tig;
                    float b0v = bp[cc], b1v = bp[cc + 1];
                    if (mra < NN)
                        *(float2*)&Y[mra * HID + cc] = make_float2(acc[mi][j][0] + b0v, acc[mi][j][1] + b1v);
                    if (mrb < NN)
                        *(float2*)&Y[mrb * HID + cc] = make_float2(acc[mi][j][2] + b0v, acc[mi][j][3] + b1v);
                }
            } else {
                int boff = (sel == 1) ? 1 : 0;
                #pragma unroll
                for (int j = 0; j < 4; j++) {
                    int cc = (((nq * 4 + j) * 8) & 63) + 2 * tig;
                    float b0v = bp[cc], b1v = bp[cc + 1];
                    if (mra < NN)
                        g_BD[mra * 64 + cc + boff] = pack_bf16x2(acc[mi][j][0] + b0v, acc[mi][j][1] + b1v);
                    if (mrb < NN)
                        g_BD[mrb * 64 + cc + boff] = pack_bf16x2(acc[mi][j][2] + b0v, acc[mi][j][3] + b1v);
                }
            }
        }
    }
}

// ---------------- edge aggregation + fused BN stats (8-edge unrolled) ---------
__global__ __launch_bounds__(256) void k_agg(int l) {
    __shared__ float red_s[8][64], red_q[8][64];
    GDC_WAIT();
    GDC_LAUNCH();
    int w = threadIdx.x >> 5, lane = threadIdx.x & 31;
    int base = (blockIdx.x * 8 + w) * 4;
    float sx = 0.f, sy = 0.f, qx = 0.f, qy = 0.f;
    #pragma unroll 1
    for (int i = 0; i < 4; i++) {
        int gw = base + i;
        if (gw >= NN) break;
        int s0 = g_offs[gw], s1 = g_offs[gw + 1];
        int off = gw * HID + lane * 2;
        float2 el = *(const float2*)&g_E[off];
        float nx = 0.f, ny = 0.f, dx = 0.f, dy = 0.f;
        int k = s0;
        for (; k + 7 < s1; k += 8) {
            int sidx[8];
            uint2 v[8];
            #pragma unroll
            for (int j = 0; j < 8; j++) sidx[j] = g_csr[k + j];
            #pragma unroll
            for (int j = 0; j < 8; j++) v[j] = *(const uint2*)&g_BD[sidx[j] * 64 + lane * 2];
            #pragma unroll
            for (int j = 0; j < 8; j++) {
                float2 d = unpack_bf16x2(v[j].x), b = unpack_bf16x2(v[j].y);
                float gx = sigmoid_fast(d.x + el.x);
                float gy = sigmoid_fast(d.y + el.y);
                nx += gx * b.x; ny += gy * b.y;
                dx += gx;       dy += gy;
            }
        }
        for (; k + 3 < s1; k += 4) {
            int sidx[4];
            uint2 v[4];
            #pragma unroll
            for (int j = 0; j < 4; j++) sidx[j] = g_csr[k + j];
            #pragma unroll
            for (int j = 0; j < 4; j++) v[j] = *(const uint2*)&g_BD[sidx[j] * 64 + lane * 2];
            #pragma unroll
            for (int j = 0; j < 4; j++) {
                float2 d = unpack_bf16x2(v[j].x), b = unpack_bf16x2(v[j].y);
                float gx = sigmoid_fast(d.x + el.x);
                float gy = sigmoid_fast(d.y + el.y);
                nx += gx * b.x; ny += gy * b.y;
                dx += gx;       dy += gy;
            }
        }
        for (; k < s1; k++) {
            int sa = g_csr[k];
            uint2 va = *(const uint2*)&g_BD[sa * 64 + lane * 2];
            float2 d = unpack_bf16x2(va.x), b = unpack_bf16x2(va.y);
            float gx = sigmoid_fast(d.x + el.x);
            float gy = sigmoid_fast(d.y + el.y);
            nx += gx * b.x; ny += gy * b.y;
            dx += gx;       dy += gy;
        }
        float2 aa = *(const float2*)&g_A[off];
        float ox = aa.x + nx / (dx + 1e-6f);
        float oy = aa.y + ny / (dy + 1e-6f);
        *(float2*)&g_hp[off] = make_float2(ox, oy);
        sx += ox; sy += oy; qx += ox * ox; qy += oy * oy;
    }
    red_s[w][lane * 2] = sx;  red_s[w][lane * 2 + 1] = sy;
    red_q[w][lane * 2] = qx;  red_q[w][lane * 2 + 1] = qy;
    __syncthreads();
    int t = threadIdx.x;
    if (t < 64) {
        float s = 0.f, q = 0.f;
        #pragma unroll
        for (int ww = 0; ww < 8; ww++) { s += red_s[ww][t]; q += red_q[ww][t]; }
        atomicAdd(&g_stats[l][t], s);
        atomicAdd(&g_stats[l][HID + t], q);
    }
}

// ---------------- final BN/ReLU/residual -> d_out -----------------------------
__global__ __launch_bounds__(256) void k_bn_final(const float* __restrict__ gamma,
                                                  const float* __restrict__ beta,
                                                  float* __restrict__ out) {
    GDC_WAIT();
    int idx = blockIdx.x * blockDim.x + threadIdx.x;
    if (idx >= NN * HID) return;
    int c = idx & 63;
    const float* st = g_stats[NL - 1];
    const float invN = 1.f / (float)NN;
    float mu  = st[c] * invN;
    float var = st[HID + c] * invN - mu * mu;
    float xn = (g_hp[idx] - mu) * rsqrtf(var + 1e-5f);
    float v = fmaxf(gamma[c] * xn + beta[c], 0.f);
    out[idx] = g_h[idx] + v;
}

// ---------------- launch ------------------------------------------------------
extern "C" void kernel_launch(void* const* d_in, const int* in_sizes, int n_in,
                              void* d_out, int out_size) {
    const float* feature = (const float*)d_in[0];
    const int*   ei      = (const int*)d_in[1];     // int32 (JAX x64 disabled)
    const float* emb_w   = (const float*)d_in[2];
    const float* emb_b   = (const float*)d_in[3];
    const float* Aw      = (const float*)d_in[4];
    const float* Ab      = (const float*)d_in[5];
    const float* Bw      = (const float*)d_in[6];
    const float* Bb      = (const float*)d_in[7];
    const float* Dw      = (const float*)d_in[8];
    const float* Db      = (const float*)d_in[9];
    const float* Ew      = (const float*)d_in[10];
    const float* Eb      = (const float*)d_in[11];
    const float* gamma   = (const float*)d_in[12];
    const float* beta    = (const float*)d_in[13];
    float* out = (float*)d_out;

    g_pdl_attr[0].id = cudaLaunchAttributeProgrammaticStreamSerialization;
    g_pdl_attr[0].val.programmaticStreamSerializationAllowed = 1;

    auto launch_pdl = [&](void* fn, dim3 grid, dim3 block, cudaStream_t st,
                          void** args) {
        cudaLaunchConfig_t cfg = {};
        cfg.gridDim = grid; cfg.blockDim = block; cfg.stream = st;
        cfg.attrs = g_pdl_attr; cfg.numAttrs = 1;
        cudaLaunchKernelExC(&cfg, fn, args);
    };

    // fork: CSR build on side stream, GEMM chain on origin stream
    cudaEventRecord(g_hx.ev_fork, 0);
    cudaStreamWaitEvent(g_hx.s1, g_hx.ev_fork, 0);

    // s1: CSR build (hist plain; rest PDL)
    k_hist<<<(EE / 4 + 255) / 256, 256, 0, g_hx.s1>>>(ei);
    {
        void* args[] = {};
        launch_pdl((void*)k_scan1, dim3(1), dim3(256), g_hx.s1, args);
        launch_pdl((void*)k_offs, dim3(SCAN_B), dim3(256), g_hx.s1, args);
    }
    {
        void* args[] = {(void*)&ei};
        launch_pdl((void*)k_scatter, dim3((EE / 4 + 255) / 256), dim3(256),
                   g_hx.s1, args);
    }
    cudaEventRecord(g_hx.ev_join, g_hx.s1);

    // s0: weight split (plain) -> PDL chain
    k_wsplit<<<NL, 256>>>(Aw, Bw, Dw, Ew);
    {
        void* args[] = {(void*)&feature, (void*)&emb_w, (void*)&emb_b,
                        (void*)&Ab, (void*)&Bb, (void*)&Db, (void*)&Eb};
        launch_pdl((void*)k_embed_abde0, dim3((NN + 63) / 64), dim3(256), 0, args);
    }

    // join: agg needs CSR
    cudaStreamWaitEvent(0, g_hx.ev_join, 0);
    {
        int l0 = 0;
        void* args[] = {(void*)&l0};
        launch_pdl((void*)k_agg, dim3((NN + 31) / 32), dim3(256), 0, args);
    }

    for (int l = 1; l < NL; l++) {
        const float* pAb = Ab + l * HID;
        const float* pBb = Bb + l * HID;
        const float* pDb = Db + l * HID;
        const float* pEb = Eb + l * HID;
        const float* pg = gamma + (l - 1) * HID;
        const float* pb = beta  + (l - 1) * HID;
        {
            void* args[] = {(void*)&pAb, (void*)&pBb, (void*)&pDb, (void*)&pEb,
                            (void*)&pg, (void*)&pb, (void*)&l};
            launch_pdl((void*)k_abde, dim3((NN + 63) / 64), dim3(256), 0, args);
        }
        {
            void* args[] = {(void*)&l};
            launch_pdl((void*)k_agg, dim3((NN + 31) / 32), dim3(256), 0, args);
        }
    }
    {
        const float* pg = gamma + (NL - 1) * HID;
        const float* pb = beta + (NL - 1) * HID;
        void* args[] = {(void*)&pg, (void*)&pb, (void*)&out};
        launch_pdl((void*)k_bn_final, dim3((NN * HID + 255) / 256), dim3(256),
                   0, args);
    }
}